// round 10
// baseline (speedup 1.0000x reference)
#include <cuda_runtime.h>
#include <cstdint>
#include <cstddef>

// Problem constants
#define NB    4
#define NTOK  2048
#define CIN   1024
#define QKDIM 512
#define OUTCH 1024
#define NH    8
#define HD    64     // per-head qk dim
#define VD    128    // per-head value dim
#define ATT_SCALE 0.125f   // 1/sqrt(64)

// Scratch (static device globals)
static __device__ float g_Q[(size_t)NB * NH * NTOK * HD];   // [bh][tok][d']   d sigma-permuted
static __device__ float g_K[(size_t)NB * NH * NTOK * HD];   // [bh][tok][d']   d sigma-permuted
static __device__ float g_V[(size_t)NB * NH * NTOK * VD];   // [bh][tok][v]    natural (gemm out)
static __device__ float g_Vt[(size_t)NB * NH * VD * NTOK];  // [bh][v][tok']   tok sigma-permuted
static __device__ float g_Xr[(size_t)NB * NTOK * CIN];      // tf32, k-cols sigma-permuted
static __device__ float g_Wqt[(size_t)QKDIM * CIN];         // [n][k'] transposed + sigma, tf32
static __device__ float g_Wkt[(size_t)QKDIM * CIN];
static __device__ float g_Wvt[(size_t)OUTCH * CIN];

// sigma: within each 8-group, slot 2t <- index t, slot 2t+1 <- index t+4.
// True indices (t, t+4) land at adjacent slots (2t, 2t+1) -> LDS.64 frag pairs.
__device__ __forceinline__ int sig8(int x) {
    return (x & ~7) | (((x & 3) << 1) | ((x >> 2) & 1));
}

// ---------------------------------------------------------------- helpers
__device__ __forceinline__ uint32_t f2tf(float x) {
    uint32_t u;
    asm("cvt.rna.tf32.f32 %0, %1;" : "=r"(u) : "f"(x));
    return u;
}
__device__ __forceinline__ float tfround(float x) { return __uint_as_float(f2tf(x)); }
__device__ __forceinline__ void mma_tf32(float c[4], const uint32_t a[4], const uint32_t b[2]) {
    asm volatile(
        "mma.sync.aligned.m16n8k8.row.col.f32.tf32.tf32.f32 "
        "{%0,%1,%2,%3},{%4,%5,%6,%7},{%8,%9},{%0,%1,%2,%3};"
        : "+f"(c[0]), "+f"(c[1]), "+f"(c[2]), "+f"(c[3])
        : "r"(a[0]), "r"(a[1]), "r"(a[2]), "r"(a[3]), "r"(b[0]), "r"(b[1]));
}
__device__ __forceinline__ uint32_t smem_u32(const void* p) {
    return (uint32_t)__cvta_generic_to_shared(p);
}
__device__ __forceinline__ void cp16(uint32_t dst, const void* src) {
    asm volatile("cp.async.cg.shared.global [%0], [%1], 16;" :: "r"(dst), "l"(src));
}
__device__ __forceinline__ void cp_commit() { asm volatile("cp.async.commit_group;"); }

// ================================================================ preround X
// g_Xr[m][sig8(k)] = tf32(X[m][k]); one thread per 8-col group. (verified R7)
#define NXG ((size_t)NB * NTOK * CIN / 8)   // 1,048,576
__global__ __launch_bounds__(256)
void preround_x(const float4* __restrict__ X)
{
    size_t i = (size_t)blockIdx.x * 256 + threadIdx.x;
    if (i >= NXG) return;
    float4 a = X[2 * i], b = X[2 * i + 1];      // true cols 0-3, 4-7 of group
    float4 o0, o1;                              // slots 0-3 <- {0,4,1,5}; 4-7 <- {2,6,3,7}
    o0.x = tfround(a.x); o0.y = tfround(b.x); o0.z = tfround(a.y); o0.w = tfround(b.y);
    o1.x = tfround(a.z); o1.y = tfround(b.z); o1.z = tfround(a.w); o1.w = tfround(b.w);
    ((float4*)g_Xr)[2 * i]     = o0;
    ((float4*)g_Xr)[2 * i + 1] = o1;
}

// ================================================================ preround W
// Wt[n][sig8(k)] = tf32(W[k][n]) — tiled transpose, 32x32 tiles. (verified R7)
__global__ __launch_bounds__(256)
void preround_wt(const float* __restrict__ Wq, const float* __restrict__ Wk,
                 const float* __restrict__ Wv)
{
    __shared__ float tile[32][33];
    const float* W; float* Wt; int wn;
    if (blockIdx.z == 0)      { W = Wq; Wt = g_Wqt; wn = QKDIM; }
    else if (blockIdx.z == 1) { W = Wk; Wt = g_Wkt; wn = QKDIM; }
    else                      { W = Wv; Wt = g_Wvt; wn = OUTCH; }
    int n0 = blockIdx.y * 32;
    if (n0 >= wn) return;                       // uniform per block
    int k0 = blockIdx.x * 32;
    int tx = threadIdx.x, ty = threadIdx.y;     // block (32, 8)
    #pragma unroll
    for (int i = 0; i < 32; i += 8)
        tile[ty + i][tx] = W[(size_t)(k0 + ty + i) * wn + n0 + tx];
    __syncthreads();
    int kp = k0 + (((tx & 3) << 1) | ((tx >> 2) & 1)) + (tx & ~7);
    #pragma unroll
    for (int i = 0; i < 32; i += 8)
        Wt[(size_t)(n0 + ty + i) * CIN + kp] = tfround(tile[tx][ty + i]);
}

// ================================================================ V transpose
// g_Vt[bh][v][sig8(tok)] = g_V[bh][tok][v] — tiled, coalesced both sides.
__global__ __launch_bounds__(256)
void transpose_v()
{
    __shared__ float tile[32][33];
    int bh = blockIdx.z;
    int t0 = blockIdx.y * 32, v0 = blockIdx.x * 32;
    int tx = threadIdx.x, ty = threadIdx.y;     // block (32, 8)
    const float* src = g_V + ((size_t)bh * NTOK + t0) * VD + v0;
    #pragma unroll
    for (int i = 0; i < 32; i += 8)
        tile[ty + i][tx] = src[(size_t)(ty + i) * VD + tx];    // tile[tok][v]
    __syncthreads();
    float* dst = g_Vt + ((size_t)bh * VD + v0) * NTOK + t0;
    #pragma unroll
    for (int i = 0; i < 32; i += 8)
        dst[(size_t)(ty + i) * NTOK + sig8(tx)] = tile[tx][ty + i];
}

// ================================================================ QKV GEMM
// Y[8192,2048] = Xr @ Wt^T + bias. Both operands [row][k'] sigma-permuted ->
// every fragment load is a conflict-free LDS.64. BM=BN=128, BK=32, 256 thr.
// (GEMM body verified in R7; epilogue routes to fixed layouts.)
#define GP 40                       // 32 + 8 pad; 40 mod 32 = 8 -> CF paired loads
#define G_STAGE (128 * GP)
#define GEMM_SMEM_BYTES (4 * G_STAGE * 4)   // 80 KB

__global__ __launch_bounds__(256)
void qkv_gemm(const float* __restrict__ bq,
              const float* __restrict__ bk,
              const float* __restrict__ bv)
{
    extern __shared__ float sm[];
    float* As = sm;                        // [2][128][GP]
    float* Bs = sm + 2 * G_STAGE;          // [2][128][GP]

    const int tid = threadIdx.x;
    const int m0 = blockIdx.y * 128;
    const int n0 = blockIdx.x * 128;

    const float* Wsrc;
    int nc0;
    if (n0 < QKDIM)          { Wsrc = g_Wqt; nc0 = n0;            }
    else if (n0 < 2 * QKDIM) { Wsrc = g_Wkt; nc0 = n0 - QKDIM;    }
    else                     { Wsrc = g_Wvt; nc0 = n0 - 2 * QKDIM;}

    const uint32_t as_b = smem_u32(As);
    const uint32_t bs_b = smem_u32(Bs);

    auto load_stage = [&](int stage, int k0) {
        #pragma unroll
        for (int i = 0; i < 4; i++) {               // A: 128 rows x 8 chunks
            int idx = tid + 256 * i;
            int r = idx >> 3, c4 = idx & 7;
            cp16(as_b + (uint32_t)(stage * G_STAGE + r * GP + c4 * 4) * 4,
                 g_Xr + (size_t)(m0 + r) * CIN + k0 + c4 * 4);
        }
        #pragma unroll
        for (int i = 0; i < 4; i++) {               // B: 128 n-rows x 8 chunks
            int idx = tid + 256 * i;
            int r = idx >> 3, c4 = idx & 7;
            cp16(bs_b + (uint32_t)(stage * G_STAGE + r * GP + c4 * 4) * 4,
                 Wsrc + (size_t)(nc0 + r) * CIN + k0 + c4 * 4);
        }
        cp_commit();
    };

    const int wid = tid >> 5, lane = tid & 31;
    const int wm = wid & 3, wn = wid >> 2;          // warp tile: rows wm*32, cols wn*64
    const int g = lane >> 2, tg = lane & 3;

    float acc[2][8][4];
    #pragma unroll
    for (int mi = 0; mi < 2; mi++)
        #pragma unroll
        for (int ni = 0; ni < 8; ni++)
            #pragma unroll
            for (int j = 0; j < 4; j++) acc[mi][ni][j] = 0.f;

    load_stage(0, 0);

    const int KT = CIN / 32;   // 32
    for (int kt = 0; kt < KT; kt++) {
        if (kt + 1 < KT) {
            load_stage((kt + 1) & 1, (kt + 1) * 32);
            asm volatile("cp.async.wait_group 1;");
        } else {
            asm volatile("cp.async.wait_group 0;");
        }
        __syncthreads();

        const float* A  = As + (kt & 1) * G_STAGE;
        const float* Bt = Bs + (kt & 1) * G_STAGE;

        #pragma unroll
        for (int ks = 0; ks < 4; ks++) {
            uint32_t af[2][4];
            #pragma unroll
            for (int mi = 0; mi < 2; mi++) {
                int r0 = wm * 32 + mi * 16 + g;
                uint2 lo = *(const uint2*)&A[r0 * GP + ks * 8 + 2 * tg];        // (k=tg, k=tg+4)
                uint2 hi = *(const uint2*)&A[(r0 + 8) * GP + ks * 8 + 2 * tg];
                af[mi][0] = lo.x; af[mi][2] = lo.y;
                af[mi][1] = hi.x; af[mi][3] = hi.y;
            }
            #pragma unroll
            for (int ni = 0; ni < 8; ni++) {
                int col = wn * 64 + ni * 8 + g;
                uint2 bv2 = *(const uint2*)&Bt[col * GP + ks * 8 + 2 * tg];     // (k=tg, k=tg+4)
                uint32_t bf[2] = { bv2.x, bv2.y };
                mma_tf32(acc[0][ni], af[0], bf);
                mma_tf32(acc[1][ni], af[1], bf);
            }
        }
        __syncthreads();
    }

    // Epilogue: +bias, tf32-round, route (coalesced; sigma on Q/K d-cols only).
    #pragma unroll
    for (int mi = 0; mi < 2; mi++) {
        #pragma unroll
        for (int ni = 0; ni < 8; ni++) {
            #pragma unroll
            for (int j = 0; j < 4; j++) {
                int r = wm * 32 + mi * 16 + g + ((j >= 2) ? 8 : 0);
                int c = wn * 64 + ni * 8 + tg * 2 + (j & 1);
                int m = m0 + r, n = n0 + c;
                int b = m >> 11, tok = m & 2047;
                float v = acc[mi][ni][j];
                if (n < QKDIM) {
                    v = tfround(v + bq[n]);
                    int h = n >> 6, dp = sig8(n & 63);
                    g_Q[(((size_t)(b * NH + h)) * NTOK + tok) * HD + dp] = v;
                } else if (n < 2 * QKDIM) {
                    int n2 = n - QKDIM;
                    v = tfround(v + bk[n2]);
                    int h = n2 >> 6, dp = sig8(n2 & 63);
                    g_K[(((size_t)(b * NH + h)) * NTOK + tok) * HD + dp] = v;
                } else {
                    int n2 = n - 2 * QKDIM;
                    v = tfround(v + bv[n2]);
                    int h = n2 >> 7, vd = n2 & 127;
                    g_V[(((size_t)(b * NH + h)) * NTOK + tok) * VD + vd] = v;
                }
            }
        }
    }
}

// ================================================================ Attention
// 128-thread CTAs (4 warps), Br=64, Bc=64, 3 CTAs/SM (72 KB smem). Q in regs.
// All mma fragment loads are LDS.64: Q/K via sigma-d, P (written to sigma token
// slots) and V (from g_Vt, k-major, sigma tok) via sigma-token. K, V single-
// buffered with post-phase prefetch. No max-subtraction softmax.
#define QP 72     // 72 mod 32 = 8 -> all paired frag loads full-rate
#define P_FLOATS (64 * QP)            // P buffer; Q staging in prologue
#define K_FLOATS (64 * QP)
#define V_FLOATS (128 * QP)           // Vs[v][tok-slot]
#define ATT_SMEM_BYTES ((P_FLOATS + K_FLOATS + V_FLOATS) * 4)   // 73728

__global__ __launch_bounds__(128, 3)
void attn_kernel(float* __restrict__ out)
{
    extern __shared__ float sm[];
    float* Ps = sm;                       // [64][QP]  (Q staging, then P)
    float* Ks = sm + P_FLOATS;            // [64][QP]  rows = tokens (natural)
    float* Vs = Ks + K_FLOATS;            // [128][QP] rows = v, cols = tok-slots

    const int tid = threadIdx.x;
    const int qt = blockIdx.x;            // 0..31 (64-row q tiles)
    const int bh = blockIdx.y;            // 0..31
    const int b = bh >> 3, h = bh & 7;

    const float* Qg = g_Q + ((size_t)bh * NTOK + qt * 64) * HD;
    const float* Kg = g_K + (size_t)bh * NTOK * HD;
    const float* Vg = g_Vt + (size_t)bh * VD * NTOK;

    const uint32_t ps_b = smem_u32(Ps);
    const uint32_t ks_b = smem_u32(Ks);
    const uint32_t vs_b = smem_u32(Vs);

    // Stage Q into Ps (64x64 = 1024 f4)                          [group: Q]
    #pragma unroll
    for (int i = 0; i < 8; i++) {
        int idx = tid + 128 * i;
        int r = idx >> 4, c4 = idx & 15;
        cp16(ps_b + (uint32_t)(r * QP + c4 * 4) * 4, Qg + (size_t)r * HD + c4 * 4);
    }
    cp_commit();

    auto loadK = [&](int t) {
        const float* Kt = Kg + (size_t)t * 64 * HD;
        #pragma unroll
        for (int i = 0; i < 8; i++) {
            int idx = tid + 128 * i;
            int r = idx >> 4, c4 = idx & 15;
            cp16(ks_b + (uint32_t)(r * QP + c4 * 4) * 4, Kt + (size_t)r * HD + c4 * 4);
        }
        cp_commit();
    };
    auto loadV = [&](int t) {
        #pragma unroll
        for (int i = 0; i < 16; i++) {                // 128 v-rows x 16B-chunks of 64 toks
            int idx = tid + 128 * i;
            int r = idx >> 4, c4 = idx & 15;
            cp16(vs_b + (uint32_t)(r * QP + c4 * 4) * 4,
                 Vg + (size_t)r * NTOK + t * 64 + c4 * 4);
        }
        cp_commit();
    };

    loadK(0);          // pending: Q, K0
    loadV(0);          // pending: Q, K0, V0

    const int wid = tid >> 5, lane = tid & 31;
    const int g = lane >> 2, tg = lane & 3;
    const int qrow = wid * 16;
    // sigma slots of S-frag cols 2tg, 2tg+1 (token targets for P writes)
    const int sc0 = (((2 * tg) & 3) << 1) | ((2 * tg) >> 2);
    const int sc1 = (((2 * tg + 1) & 3) << 1) | ((2 * tg + 1) >> 2);

    // Q fragments -> registers (wait Q only; K0, V0 stay in flight)
    asm volatile("cp.async.wait_group 2;");
    __syncthreads();
    uint32_t aq[8][4];
    #pragma unroll
    for (int ks = 0; ks < 8; ks++) {
        uint2 lo = *(const uint2*)&Ps[(qrow + g) * QP + ks * 8 + 2 * tg];
        uint2 hi = *(const uint2*)&Ps[(qrow + g + 8) * QP + ks * 8 + 2 * tg];
        aq[ks][0] = lo.x; aq[ks][2] = lo.y;
        aq[ks][1] = hi.x; aq[ks][3] = hi.y;
    }
    // (no barrier: each warp later overwrites only its own Ps rows)

    float oacc[16][4];
    #pragma unroll
    for (int ni = 0; ni < 16; ni++)
        #pragma unroll
        for (int j = 0; j < 4; j++) oacc[ni][j] = 0.f;
    float rsum0 = 0.f, rsum1 = 0.f;

    const int TT = NTOK / 64;   // 32 key tiles
    for (int t = 0; t < TT; t++) {
        // K(t) ready (V(t) may stay pending)
        asm volatile("cp.async.wait_group 1;");
        __syncthreads();

        // ---- S = Q @ K^T  (warp: 16 x 64; k = d, sigma slots) ----
        float s[8][4];
        #pragma unroll
        for (int ni = 0; ni < 8; ni++)
            #pragma unroll
            for (int j = 0; j < 4; j++) s[ni][j] = 0.f;

        #pragma unroll
        for (int ks = 0; ks < 8; ks++) {
            #pragma unroll
            for (int ni = 0; ni < 8; ni++) {
                uint2 bv2 = *(const uint2*)&Ks[(8 * ni + g) * QP + ks * 8 + 2 * tg];
                uint32_t bf[2] = { bv2.x, bv2.y };
                mma_tf32(s[ni], aq[ks], bf);
            }
        }

        __syncthreads();                 // all warps done reading K(t)
        if (t + 1 < TT) loadK(t + 1);    // prefetch next K into the K buffer

        // ---- exp + row-sum; P written to sigma token slots ----
        float ls0 = 0.f, ls1 = 0.f;
        #pragma unroll
        for (int ni = 0; ni < 8; ni++) {
            float e0 = __expf(s[ni][0] * ATT_SCALE);   // token 8ni+2tg,   row g
            float e1 = __expf(s[ni][1] * ATT_SCALE);   // token 8ni+2tg+1, row g
            float e2 = __expf(s[ni][2] * ATT_SCALE);   // token 8ni+2tg,   row g+8
            float e3 = __expf(s[ni][3] * ATT_SCALE);
            ls0 += e0 + e1;
            ls1 += e2 + e3;
            Ps[(qrow + g) * QP + ni * 8 + sc0]     = tfround(e0);
            Ps[(qrow + g) * QP + ni * 8 + sc1]     = tfround(e1);
            Ps[(qrow + g + 8) * QP + ni * 8 + sc0] = tfround(e2);
            Ps[(qrow + g + 8) * QP + ni * 8 + sc1] = tfround(e3);
        }
        ls0 += __shfl_xor_sync(0xffffffffu, ls0, 1);
        ls0 += __shfl_xor_sync(0xffffffffu, ls0, 2);
        ls1 += __shfl_xor_sync(0xffffffffu, ls1, 1);
        ls1 += __shfl_xor_sync(0xffffffffu, ls1, 2);
        rsum0 += ls0;
        rsum1 += ls1;

        // V(t) ready (pending: K(t+1) if issued)
        if (t + 1 < TT) { asm volatile("cp.async.wait_group 1;"); }
        else            { asm volatile("cp.async.wait_group 0;"); }
        __syncthreads();

        // ---- O += P @ V  (warp: 16 x 128; k = token sigma slots) ----
        #pragma unroll
        for (int ks = 0; ks < 8; ks++) {
            uint2 lo = *(const uint2*)&Ps[(qrow + g) * QP + ks * 8 + 2 * tg];
            uint2 hi = *(const uint2*)&Ps[(qrow + g + 8) * QP + ks * 8 + 2 * tg];
            uint32_t af[4] = { lo.x, hi.x, lo.y, hi.y };
            #pragma unroll
            for (int ni = 0; ni < 16; ni++) {
                uint2 bv2 = *(const uint2*)&Vs[(ni * 8 + g) * QP + ks * 8 + 2 * tg];
                uint32_t bf[2] = { bv2.x, bv2.y };
                mma_tf32(oacc[ni], af, bf);
            }
        }

        __syncthreads();                 // all warps done reading V(t)
        if (t + 1 < TT) loadV(t + 1);    // prefetch next V into the V buffer
    }

    // ---- normalize + store: out[b][tok][h*128 + v] ----
    const float inv0 = 1.f / rsum0;
    const float inv1 = 1.f / rsum1;
    const int tok0 = qt * 64 + qrow + g;
    float* op = out + ((size_t)b * NTOK) * OUTCH + (size_t)h * VD;
    #pragma unroll
    for (int ni = 0; ni < 16; ni++) {
        int v = ni * 8 + tg * 2;
        op[(size_t)tok0 * OUTCH + v]           = oacc[ni][0] * inv0;
        op[(size_t)tok0 * OUTCH + v + 1]       = oacc[ni][1] * inv0;
        op[(size_t)(tok0 + 8) * OUTCH + v]     = oacc[ni][2] * inv1;
        op[(size_t)(tok0 + 8) * OUTCH + v + 1] = oacc[ni][3] * inv1;
    }
}

// ================================================================ launch
extern "C" void kernel_launch(void* const* d_in, const int* in_sizes, int n_in,
                              void* d_out, int out_size)
{
    const float* x  = (const float*)d_in[0];
    const float* Wq = (const float*)d_in[1];
    const float* bq = (const float*)d_in[2];
    const float* Wk = (const float*)d_in[3];
    const float* bk = (const float*)d_in[4];
    const float* Wv = (const float*)d_in[5];
    const float* bv = (const float*)d_in[6];
    float* out = (float*)d_out;

    cudaFuncSetAttribute(qkv_gemm, cudaFuncAttributeMaxDynamicSharedMemorySize,
                         GEMM_SMEM_BYTES);
    cudaFuncSetAttribute(attn_kernel, cudaFuncAttributeMaxDynamicSharedMemorySize,
                         ATT_SMEM_BYTES);

    preround_x<<<(unsigned)((NXG + 255) / 256), 256>>>((const float4*)x);
    preround_wt<<<dim3(CIN / 32, OUTCH / 32, 3), dim3(32, 8)>>>(Wq, Wk, Wv);

    dim3 g1(OUTCH * 2 / 128 /*16*/, (NB * NTOK) / 128 /*64*/);
    qkv_gemm<<<g1, 256, GEMM_SMEM_BYTES>>>(bq, bk, bv);

    transpose_v<<<dim3(VD / 32, NTOK / 32, NB * NH), dim3(32, 8)>>>();

    dim3 g2(NTOK / 64 /*32*/, NB * NH /*32*/);
    attn_kernel<<<g2, 128, ATT_SMEM_BYTES>>>(out);
}

// round 12
// speedup vs baseline: 1.0245x; 1.0245x over previous
#include <cuda_runtime.h>
#include <cstdint>
#include <cstddef>

// Problem constants
#define NB    4
#define NTOK  2048
#define CIN   1024
#define QKDIM 512
#define OUTCH 1024
#define NH    8
#define HD    64     // per-head qk dim
#define VD    128    // per-head value dim
#define ATT_SCALE 0.125f   // 1/sqrt(64)

// Scratch (static device globals)
static __device__ float g_Q[(size_t)NB * NH * NTOK * HD];   // [bh][tok][d]  tf32
static __device__ float g_K[(size_t)NB * NH * NTOK * HD];   // [bh][tok][d]  tf32
static __device__ float g_V[(size_t)NB * NH * NTOK * VD];   // [bh][tok][v]  tf32
static __device__ float g_Xr[(size_t)NB * NTOK * CIN];      // tf32-rounded X
static __device__ float g_Wqr[(size_t)CIN * QKDIM];
static __device__ float g_Wkr[(size_t)CIN * QKDIM];
static __device__ float g_Wvr[(size_t)CIN * OUTCH];

// ---------------------------------------------------------------- helpers
__device__ __forceinline__ uint32_t f2tf(float x) {
    uint32_t u;
    asm("cvt.rna.tf32.f32 %0, %1;" : "=r"(u) : "f"(x));
    return u;
}
__device__ __forceinline__ float tfround(float x) { return __uint_as_float(f2tf(x)); }
__device__ __forceinline__ void mma_tf32(float c[4], const uint32_t a[4], const uint32_t b[2]) {
    asm volatile(
        "mma.sync.aligned.m16n8k8.row.col.f32.tf32.tf32.f32 "
        "{%0,%1,%2,%3},{%4,%5,%6,%7},{%8,%9},{%0,%1,%2,%3};"
        : "+f"(c[0]), "+f"(c[1]), "+f"(c[2]), "+f"(c[3])
        : "r"(a[0]), "r"(a[1]), "r"(a[2]), "r"(a[3]), "r"(b[0]), "r"(b[1]));
}
__device__ __forceinline__ uint32_t smem_u32(const void* p) {
    return (uint32_t)__cvta_generic_to_shared(p);
}
__device__ __forceinline__ void cp16(uint32_t dst, const void* src) {
    asm volatile("cp.async.cg.shared.global [%0], [%1], 16;" :: "r"(dst), "l"(src));
}
__device__ __forceinline__ void cp_commit() { asm volatile("cp.async.commit_group;"); }

// ================================================================ Pre-round
#define NX4  ((NB * NTOK * CIN) / 4)
#define NQ4  ((CIN * QKDIM) / 4)
#define NV4  ((CIN * OUTCH) / 4)
#define NTOT4 (NX4 + 2 * NQ4 + NV4)

__global__ __launch_bounds__(256)
void preround_kernel(const float4* __restrict__ X, const float4* __restrict__ Wq,
                     const float4* __restrict__ Wk, const float4* __restrict__ Wv)
{
    for (size_t i = (size_t)blockIdx.x * blockDim.x + threadIdx.x;
         i < NTOT4; i += (size_t)gridDim.x * blockDim.x) {
        float4 v; float4* dst;
        if (i < NX4)                { v = X[i];                  dst = ((float4*)g_Xr)  + i; }
        else if (i < NX4 + NQ4)     { v = Wq[i - NX4];           dst = ((float4*)g_Wqr) + (i - NX4); }
        else if (i < NX4 + 2 * NQ4) { v = Wk[i - NX4 - NQ4];     dst = ((float4*)g_Wkr) + (i - NX4 - NQ4); }
        else                        { v = Wv[i - NX4 - 2 * NQ4]; dst = ((float4*)g_Wvr) + (i - NX4 - 2 * NQ4); }
        v.x = tfround(v.x); v.y = tfround(v.y); v.z = tfround(v.z); v.w = tfround(v.w);
        *dst = v;
    }
}

// ================================================================ QKV GEMM (known-good legacy)
#define GA_PITCH 36
#define GB_PITCH 136
#define GA_STAGE (128 * GA_PITCH)
#define GB_STAGE (32 * GB_PITCH)
#define GEMM_SMEM_BYTES ((2 * GA_STAGE + 2 * GB_STAGE) * 4)

__global__ __launch_bounds__(256)
void qkv_gemm(const float* __restrict__ bq, const float* __restrict__ bk,
              const float* __restrict__ bv)
{
    extern __shared__ float sm[];
    float* As = sm;
    float* Bs = sm + 2 * GA_STAGE;

    const int tid = threadIdx.x;
    const int m0 = blockIdx.y * 128;
    const int n0 = blockIdx.x * 128;

    const float* Wsrc;
    int wld, nc0;
    if (n0 < QKDIM)          { Wsrc = g_Wqr; wld = QKDIM; nc0 = n0;            }
    else if (n0 < 2 * QKDIM) { Wsrc = g_Wkr; wld = QKDIM; nc0 = n0 - QKDIM;    }
    else                     { Wsrc = g_Wvr; wld = OUTCH; nc0 = n0 - 2*QKDIM;  }

    const uint32_t as_b = smem_u32(As);
    const uint32_t bs_b = smem_u32(Bs);

    auto load_stage = [&](int stage, int k0) {
        #pragma unroll
        for (int i = 0; i < 4; i++) {
            int idx = tid + 256 * i;
            int r = idx >> 3, c4 = idx & 7;
            cp16(as_b + (uint32_t)(stage * GA_STAGE + r * GA_PITCH + c4 * 4) * 4,
                 g_Xr + (size_t)(m0 + r) * CIN + k0 + c4 * 4);
        }
        #pragma unroll
        for (int i = 0; i < 4; i++) {
            int idx = tid + 256 * i;
            int r = idx >> 5, c4 = idx & 31;
            cp16(bs_b + (uint32_t)(stage * GB_STAGE + r * GB_PITCH + c4 * 4) * 4,
                 Wsrc + (size_t)(k0 + r) * wld + nc0 + c4 * 4);
        }
        cp_commit();
    };

    const int wid = tid >> 5, lane = tid & 31;
    const int wm = wid & 3, wn = wid >> 2;
    const int g = lane >> 2, tg = lane & 3;

    float acc[2][8][4];
    #pragma unroll
    for (int mi = 0; mi < 2; mi++)
        #pragma unroll
        for (int ni = 0; ni < 8; ni++)
            #pragma unroll
            for (int j = 0; j < 4; j++) acc[mi][ni][j] = 0.f;

    load_stage(0, 0);

    const int KT = CIN / 32;
    for (int kt = 0; kt < KT; kt++) {
        if (kt + 1 < KT) {
            load_stage((kt + 1) & 1, (kt + 1) * 32);
            asm volatile("cp.async.wait_group 1;");
        } else {
            asm volatile("cp.async.wait_group 0;");
        }
        __syncthreads();

        const float* A  = As + (kt & 1) * GA_STAGE;
        const float* Bt = Bs + (kt & 1) * GB_STAGE;

        #pragma unroll
        for (int ks = 0; ks < 4; ks++) {
            uint32_t af[2][4];
            #pragma unroll
            for (int mi = 0; mi < 2; mi++) {
                int r0 = wm * 32 + mi * 16 + g;
                af[mi][0] = __float_as_uint(A[r0 * GA_PITCH + ks * 8 + tg]);
                af[mi][1] = __float_as_uint(A[(r0 + 8) * GA_PITCH + ks * 8 + tg]);
                af[mi][2] = __float_as_uint(A[r0 * GA_PITCH + ks * 8 + tg + 4]);
                af[mi][3] = __float_as_uint(A[(r0 + 8) * GA_PITCH + ks * 8 + tg + 4]);
            }
            #pragma unroll
            for (int ni = 0; ni < 8; ni++) {
                int col = wn * 64 + ni * 8 + g;
                uint32_t bf[2];
                bf[0] = __float_as_uint(Bt[(ks * 8 + tg) * GB_PITCH + col]);
                bf[1] = __float_as_uint(Bt[(ks * 8 + tg + 4) * GB_PITCH + col]);
                mma_tf32(acc[0][ni], af[0], bf);
                mma_tf32(acc[1][ni], af[1], bf);
            }
        }
        __syncthreads();
    }

    #pragma unroll
    for (int mi = 0; mi < 2; mi++) {
        #pragma unroll
        for (int ni = 0; ni < 8; ni++) {
            #pragma unroll
            for (int j = 0; j < 4; j++) {
                int r = wm * 32 + mi * 16 + g + ((j >= 2) ? 8 : 0);
                int c = wn * 64 + ni * 8 + tg * 2 + (j & 1);
                int m = m0 + r, n = n0 + c;
                int b = m >> 11, tok = m & 2047;
                float v = acc[mi][ni][j];
                if (n < QKDIM) {
                    v = tfround(v + bq[n]);
                    int h = n >> 6, d = n & 63;
                    g_Q[(((size_t)(b * NH + h)) * NTOK + tok) * HD + d] = v;
                } else if (n < 2 * QKDIM) {
                    int n2 = n - QKDIM;
                    v = tfround(v + bk[n2]);
                    int h = n2 >> 6, d = n2 & 63;
                    g_K[(((size_t)(b * NH + h)) * NTOK + tok) * HD + d] = v;
                } else {
                    int n2 = n - 2 * QKDIM;
                    v = tfround(v + bv[n2]);
                    int h = n2 >> 7, vd = n2 & 127;
                    g_V[(((size_t)(b * NH + h)) * NTOK + tok) * VD + vd] = v;
                }
            }
        }
    }
}

// ================================================================ Attention
// Br=64, Bc=64, 128 threads, 4 warps tiled 2m x 2n:
//   S:   warp = 32 q-rows x 32 keys   (K frags shared across 2 m-tiles)
//   P@V: warp = 32 q-rows x 64 v-cols (V frags shared across 2 m-tiles)
// Halves B-operand smem-byte traffic vs 16-row warps (the binding resource:
// L1tex wavefronts). Q frags in regs; per-tile shuffles removed — row sums
// kept as per-lane partials, reduced once in the epilogue via smem.
// K and V single-buffered with post-phase prefetch (R8 pipeline, verified).
#define QP 68     // 68 mod 32 = 4 -> Q/K/P frag reads bank 4g+tg = lane (CF)
#define VP 136    // 136 mod 32 = 8 -> V frag reads bank 8tg+g = perm(lane) (CF)
#define P_FLOATS (64 * QP)            // P buffer; Q staging; RS in epilogue
#define K_FLOATS (64 * QP)
#define V_FLOATS (64 * VP)
#define ATT_SMEM_BYTES ((P_FLOATS + K_FLOATS + V_FLOATS) * 4)   // 69632

__global__ __launch_bounds__(128, 2)
void attn_kernel(float* __restrict__ out)
{
    extern __shared__ float sm[];
    float* Ps = sm;                       // [64][QP]
    float* Ks = sm + P_FLOATS;            // [64][QP]
    float* Vs = Ks + K_FLOATS;            // [64][VP]

    const int tid = threadIdx.x;
    const int qt = blockIdx.x;            // 0..31 (64-row q tiles)
    const int bh = blockIdx.y;            // 0..31
    const int b = bh >> 3, h = bh & 7;

    const float* Qg = g_Q + ((size_t)bh * NTOK + qt * 64) * HD;
    const float* Kg = g_K + (size_t)bh * NTOK * HD;
    const float* Vg = g_V + (size_t)bh * NTOK * VD;

    const uint32_t ps_b = smem_u32(Ps);
    const uint32_t ks_b = smem_u32(Ks);
    const uint32_t vs_b = smem_u32(Vs);

    // Stage Q into Ps (64x64 = 1024 f4)                          [group: Q]
    #pragma unroll
    for (int i = 0; i < 8; i++) {
        int idx = tid + 128 * i;
        int r = idx >> 4, c4 = idx & 15;
        cp16(ps_b + (uint32_t)(r * QP + c4 * 4) * 4, Qg + (size_t)r * HD + c4 * 4);
    }
    cp_commit();

    auto loadK = [&](int t) {
        const float* Kt = Kg + (size_t)t * 64 * HD;
        #pragma unroll
        for (int i = 0; i < 8; i++) {
            int idx = tid + 128 * i;
            int r = idx >> 4, c4 = idx & 15;
            cp16(ks_b + (uint32_t)(r * QP + c4 * 4) * 4, Kt + (size_t)r * HD + c4 * 4);
        }
        cp_commit();
    };
    auto loadV = [&](int t) {
        const float* Vt = Vg + (size_t)t * 64 * VD;
        #pragma unroll
        for (int i = 0; i < 16; i++) {
            int idx = tid + 128 * i;
            int r = idx >> 5, c4 = idx & 31;
            cp16(vs_b + (uint32_t)(r * VP + c4 * 4) * 4, Vt + (size_t)r * VD + c4 * 4);
        }
        cp_commit();
    };

    loadK(0);          // pending: Q, K0
    loadV(0);          // pending: Q, K0, V0

    const int wid = tid >> 5, lane = tid & 31;
    const int g = lane >> 2, tg = lane & 3;
    const int wm = wid & 1, wn = wid >> 1;
    const int r0 = wm * 32;               // warp q-row base (32 rows)
    const int kc = wn * 32;               // warp S key-column base
    const int vc = wn * 64;               // warp P@V v-column base

    // Q fragments -> registers (2 m-tiles). Wait Q only; K0, V0 in flight.
    asm volatile("cp.async.wait_group 2;");
    __syncthreads();
    uint32_t aq[2][8][4];
    #pragma unroll
    for (int mi = 0; mi < 2; mi++) {
        int rr = r0 + mi * 16 + g;
        #pragma unroll
        for (int ks = 0; ks < 8; ks++) {
            aq[mi][ks][0] = __float_as_uint(Ps[rr * QP + ks * 8 + tg]);
            aq[mi][ks][1] = __float_as_uint(Ps[(rr + 8) * QP + ks * 8 + tg]);
            aq[mi][ks][2] = __float_as_uint(Ps[rr * QP + ks * 8 + tg + 4]);
            aq[mi][ks][3] = __float_as_uint(Ps[(rr + 8) * QP + ks * 8 + tg + 4]);
        }
    }
    // (no extra barrier needed: loop-top __syncthreads orders aq reads of all
    //  warps before the first softmax P-writes touch shared rows)

    float oacc[2][8][4];
    #pragma unroll
    for (int mi = 0; mi < 2; mi++)
        #pragma unroll
        for (int ni = 0; ni < 8; ni++)
            #pragma unroll
            for (int j = 0; j < 4; j++) oacc[mi][ni][j] = 0.f;
    float rs[2][2] = {{0.f, 0.f}, {0.f, 0.f}};   // per-lane partial row sums

    const int TT = NTOK / 64;   // 32 key tiles
    for (int t = 0; t < TT; t++) {
        // K(t) ready (V(t) may stay pending)
        asm volatile("cp.async.wait_group 1;");
        __syncthreads();

        // ---- S = Q @ K^T  (warp: 32 rows x 32 keys) ----
        float s[2][4][4];
        #pragma unroll
        for (int mi = 0; mi < 2; mi++)
            #pragma unroll
            for (int ni = 0; ni < 4; ni++)
                #pragma unroll
                for (int j = 0; j < 4; j++) s[mi][ni][j] = 0.f;

        #pragma unroll
        for (int ks = 0; ks < 8; ks++) {
            #pragma unroll
            for (int ni = 0; ni < 4; ni++) {
                uint32_t bf[2];
                bf[0] = __float_as_uint(Ks[(kc + ni * 8 + g) * QP + ks * 8 + tg]);
                bf[1] = __float_as_uint(Ks[(kc + ni * 8 + g) * QP + ks * 8 + tg + 4]);
                mma_tf32(s[0][ni], aq[0][ks], bf);
                mma_tf32(s[1][ni], aq[1][ks], bf);
            }
        }

        __syncthreads();                 // all warps done reading K(t)
        if (t + 1 < TT) loadK(t + 1);    // prefetch next K into the K buffer

        // ---- exp + per-lane partial row sums; stage P quadrant ----
        #pragma unroll
        for (int mi = 0; mi < 2; mi++) {
            int rr = r0 + mi * 16 + g;
            #pragma unroll
            for (int ni = 0; ni < 4; ni++) {
                float e0 = __expf(s[mi][ni][0] * ATT_SCALE);
                float e1 = __expf(s[mi][ni][1] * ATT_SCALE);
                float e2 = __expf(s[mi][ni][2] * ATT_SCALE);
                float e3 = __expf(s[mi][ni][3] * ATT_SCALE);
                rs[mi][0] += e0 + e1;    // row rr
                rs[mi][1] += e2 + e3;    // row rr+8
                Ps[rr * QP + kc + ni * 8 + tg * 2]           = tfround(e0);
                Ps[rr * QP + kc + ni * 8 + tg * 2 + 1]       = tfround(e1);
                Ps[(rr + 8) * QP + kc + ni * 8 + tg * 2]     = tfround(e2);
                Ps[(rr + 8) * QP + kc + ni * 8 + tg * 2 + 1] = tfround(e3);
            }
        }

        // V(t) ready (pending: K(t+1) if issued)
        if (t + 1 < TT) { asm volatile("cp.async.wait_group 1;"); }
        else            { asm volatile("cp.async.wait_group 0;"); }
        __syncthreads();                 // P complete (all quadrants) + V landed

        // ---- O += P @ V  (warp: 32 rows x 64 v-cols, k = 64 keys) ----
        #pragma unroll
        for (int ks = 0; ks < 8; ks++) {
            uint32_t af[2][4];
            #pragma unroll
            for (int mi = 0; mi < 2; mi++) {
                int rr = r0 + mi * 16 + g;
                af[mi][0] = __float_as_uint(Ps[rr * QP + ks * 8 + tg]);
                af[mi][1] = __float_as_uint(Ps[(rr + 8) * QP + ks * 8 + tg]);
                af[mi][2] = __float_as_uint(Ps[rr * QP + ks * 8 + tg + 4]);
                af[mi][3] = __float_as_uint(Ps[(rr + 8) * QP + ks * 8 + tg + 4]);
            }
            #pragma unroll
            for (int ni = 0; ni < 8; ni++) {
                uint32_t bf[2];
                bf[0] = __float_as_uint(Vs[(ks * 8 + tg) * VP + vc + ni * 8 + g]);
                bf[1] = __float_as_uint(Vs[(ks * 8 + tg + 4) * VP + vc + ni * 8 + g]);
                mma_tf32(oacc[0][ni], af[0], bf);
                mma_tf32(oacc[1][ni], af[1], bf);
            }
        }

        __syncthreads();                 // all warps done reading V(t) and P
        if (t + 1 < TT) loadV(t + 1);    // prefetch next V into the V buffer
    }

    // ---- epilogue: reduce row sums (intra-warp over tg, cross-warp via smem) ----
    #pragma unroll
    for (int mi = 0; mi < 2; mi++)
        #pragma unroll
        for (int hf = 0; hf < 2; hf++) {
            float v = rs[mi][hf];
            v += __shfl_xor_sync(0xffffffffu, v, 1);
            v += __shfl_xor_sync(0xffffffffu, v, 2);
            rs[mi][hf] = v;
        }
    float* RS = Ps;                      // [2 wn][64 rows]; Ps is free now
    if (tg == 0) {
        #pragma unroll
        for (int mi = 0; mi < 2; mi++)
            #pragma unroll
            for (int hf = 0; hf < 2; hf++)
                RS[wn * 64 + r0 + mi * 16 + hf * 8 + g] = rs[mi][hf];
    }
    __syncthreads();

    #pragma unroll
    for (int mi = 0; mi < 2; mi++) {
        int rr = r0 + mi * 16 + g;
        float inv0 = 1.f / (RS[rr] + RS[64 + rr]);
        float inv1 = 1.f / (RS[rr + 8] + RS[64 + rr + 8]);
        int tokA = qt * 64 + rr;
        float* op = out + ((size_t)b * NTOK + tokA) * OUTCH + (size_t)h * VD + vc;
        #pragma unroll
        for (int ni = 0; ni < 8; ni++) {
            int c = ni * 8 + tg * 2;
            op[c]                  = oacc[mi][ni][0] * inv0;
            op[c + 1]              = oacc[mi][ni][1] * inv0;
            op[8 * OUTCH + c]      = oacc[mi][ni][2] * inv1;
            op[8 * OUTCH + c + 1]  = oacc[mi][ni][3] * inv1;
        }
    }
}

// ================================================================ launch
extern "C" void kernel_launch(void* const* d_in, const int* in_sizes, int n_in,
                              void* d_out, int out_size)
{
    const float* x  = (const float*)d_in[0];
    const float* Wq = (const float*)d_in[1];
    const float* bq = (const float*)d_in[2];
    const float* Wk = (const float*)d_in[3];
    const float* bk = (const float*)d_in[4];
    const float* Wv = (const float*)d_in[5];
    const float* bv = (const float*)d_in[6];
    float* out = (float*)d_out;

    cudaFuncSetAttribute(qkv_gemm, cudaFuncAttributeMaxDynamicSharedMemorySize,
                         GEMM_SMEM_BYTES);
    cudaFuncSetAttribute(attn_kernel, cudaFuncAttributeMaxDynamicSharedMemorySize,
                         ATT_SMEM_BYTES);

    preround_kernel<<<2048, 256>>>((const float4*)x, (const float4*)Wq,
                                   (const float4*)Wk, (const float4*)Wv);

    dim3 g1(OUTCH * 2 / 128, (NB * NTOK) / 128);
    qkv_gemm<<<g1, 256, GEMM_SMEM_BYTES>>>(bq, bk, bv);

    dim3 g2(NTOK / 64, NB * NH);
    attn_kernel<<<g2, 128, ATT_SMEM_BYTES>>>(out);
}

// round 13
// speedup vs baseline: 1.0283x; 1.0037x over previous
#include <cuda_runtime.h>
#include <cstdint>
#include <cstddef>

// Problem constants
#define NB    4
#define NTOK  2048
#define CIN   1024
#define QKDIM 512
#define OUTCH 1024
#define NH    8
#define HD    64     // per-head qk dim
#define VD    128    // per-head value dim
#define ATT_SCALE 0.125f   // 1/sqrt(64)

// Scratch (static device globals)
static __device__ float g_Q[(size_t)NB * NH * NTOK * HD];   // [bh][tok][d]  tf32
static __device__ float g_K[(size_t)NB * NH * NTOK * HD];   // [bh][tok][d]  tf32
static __device__ float g_V[(size_t)NB * NH * NTOK * VD];   // [bh][tok][v]  tf32
static __device__ float g_Xr[(size_t)NB * NTOK * CIN];      // tf32-rounded X
static __device__ float g_Wqr[(size_t)CIN * QKDIM];
static __device__ float g_Wkr[(size_t)CIN * QKDIM];
static __device__ float g_Wvr[(size_t)CIN * OUTCH];

// ---------------------------------------------------------------- helpers
__device__ __forceinline__ uint32_t f2tf(float x) {
    uint32_t u;
    asm("cvt.rna.tf32.f32 %0, %1;" : "=r"(u) : "f"(x));
    return u;
}
__device__ __forceinline__ float tfround(float x) { return __uint_as_float(f2tf(x)); }
__device__ __forceinline__ void mma_tf32(float c[4], const uint32_t a[4], const uint32_t b[2]) {
    asm volatile(
        "mma.sync.aligned.m16n8k8.row.col.f32.tf32.tf32.f32 "
        "{%0,%1,%2,%3},{%4,%5,%6,%7},{%8,%9},{%0,%1,%2,%3};"
        : "+f"(c[0]), "+f"(c[1]), "+f"(c[2]), "+f"(c[3])
        : "r"(a[0]), "r"(a[1]), "r"(a[2]), "r"(a[3]), "r"(b[0]), "r"(b[1]));
}
__device__ __forceinline__ uint32_t smem_u32(const void* p) {
    return (uint32_t)__cvta_generic_to_shared(p);
}
__device__ __forceinline__ void cp16(uint32_t dst, const void* src) {
    asm volatile("cp.async.cg.shared.global [%0], [%1], 16;" :: "r"(dst), "l"(src));
}
__device__ __forceinline__ void cp_commit() { asm volatile("cp.async.commit_group;"); }

// ================================================================ Pre-round X  (launch idx 0)
#define NX4  ((NB * NTOK * CIN) / 4)
__global__ __launch_bounds__(256)
void preround_x(const float4* __restrict__ X)
{
    for (size_t i = (size_t)blockIdx.x * blockDim.x + threadIdx.x;
         i < NX4; i += (size_t)gridDim.x * blockDim.x) {
        float4 v = X[i];
        v.x = tfround(v.x); v.y = tfround(v.y); v.z = tfround(v.z); v.w = tfround(v.w);
        ((float4*)g_Xr)[i] = v;
    }
}

// ================================================================ Pre-round W  (launch idx 1)
#define NQ4  ((CIN * QKDIM) / 4)
#define NV4  ((CIN * OUTCH) / 4)
#define NW4  (2 * NQ4 + NV4)
__global__ __launch_bounds__(256)
void preround_w(const float4* __restrict__ Wq, const float4* __restrict__ Wk,
                const float4* __restrict__ Wv)
{
    for (size_t i = (size_t)blockIdx.x * blockDim.x + threadIdx.x;
         i < NW4; i += (size_t)gridDim.x * blockDim.x) {
        float4 v; float4* dst;
        if (i < NQ4)            { v = Wq[i];           dst = ((float4*)g_Wqr) + i; }
        else if (i < 2 * NQ4)   { v = Wk[i - NQ4];     dst = ((float4*)g_Wkr) + (i - NQ4); }
        else                    { v = Wv[i - 2 * NQ4]; dst = ((float4*)g_Wvr) + (i - 2 * NQ4); }
        v.x = tfround(v.x); v.y = tfround(v.y); v.z = tfround(v.z); v.w = tfround(v.w);
        *dst = v;
    }
}

// ================================================================ QKV GEMM (known-good, unchanged)
#define GA_PITCH 36
#define GB_PITCH 136
#define GA_STAGE (128 * GA_PITCH)
#define GB_STAGE (32 * GB_PITCH)
#define GEMM_SMEM_BYTES ((2 * GA_STAGE + 2 * GB_STAGE) * 4)

__global__ __launch_bounds__(256)
void qkv_gemm(const float* __restrict__ bq, const float* __restrict__ bk,
              const float* __restrict__ bv)
{
    extern __shared__ float sm[];
    float* As = sm;
    float* Bs = sm + 2 * GA_STAGE;

    const int tid = threadIdx.x;
    const int m0 = blockIdx.y * 128;
    const int n0 = blockIdx.x * 128;

    const float* Wsrc;
    int wld, nc0;
    if (n0 < QKDIM)          { Wsrc = g_Wqr; wld = QKDIM; nc0 = n0;            }
    else if (n0 < 2 * QKDIM) { Wsrc = g_Wkr; wld = QKDIM; nc0 = n0 - QKDIM;    }
    else                     { Wsrc = g_Wvr; wld = OUTCH; nc0 = n0 - 2*QKDIM;  }

    const uint32_t as_b = smem_u32(As);
    const uint32_t bs_b = smem_u32(Bs);

    auto load_stage = [&](int stage, int k0) {
        #pragma unroll
        for (int i = 0; i < 4; i++) {
            int idx = tid + 256 * i;
            int r = idx >> 3, c4 = idx & 7;
            cp16(as_b + (uint32_t)(stage * GA_STAGE + r * GA_PITCH + c4 * 4) * 4,
                 g_Xr + (size_t)(m0 + r) * CIN + k0 + c4 * 4);
        }
        #pragma unroll
        for (int i = 0; i < 4; i++) {
            int idx = tid + 256 * i;
            int r = idx >> 5, c4 = idx & 31;
            cp16(bs_b + (uint32_t)(stage * GB_STAGE + r * GB_PITCH + c4 * 4) * 4,
                 Wsrc + (size_t)(k0 + r) * wld + nc0 + c4 * 4);
        }
        cp_commit();
    };

    const int wid = tid >> 5, lane = tid & 31;
    const int wm = wid & 3, wn = wid >> 2;
    const int g = lane >> 2, tg = lane & 3;

    float acc[2][8][4];
    #pragma unroll
    for (int mi = 0; mi < 2; mi++)
        #pragma unroll
        for (int ni = 0; ni < 8; ni++)
            #pragma unroll
            for (int j = 0; j < 4; j++) acc[mi][ni][j] = 0.f;

    load_stage(0, 0);

    const int KT = CIN / 32;
    for (int kt = 0; kt < KT; kt++) {
        if (kt + 1 < KT) {
            load_stage((kt + 1) & 1, (kt + 1) * 32);
            asm volatile("cp.async.wait_group 1;");
        } else {
            asm volatile("cp.async.wait_group 0;");
        }
        __syncthreads();

        const float* A  = As + (kt & 1) * GA_STAGE;
        const float* Bt = Bs + (kt & 1) * GB_STAGE;

        #pragma unroll
        for (int ks = 0; ks < 4; ks++) {
            uint32_t af[2][4];
            #pragma unroll
            for (int mi = 0; mi < 2; mi++) {
                int r0 = wm * 32 + mi * 16 + g;
                af[mi][0] = __float_as_uint(A[r0 * GA_PITCH + ks * 8 + tg]);
                af[mi][1] = __float_as_uint(A[(r0 + 8) * GA_PITCH + ks * 8 + tg]);
                af[mi][2] = __float_as_uint(A[r0 * GA_PITCH + ks * 8 + tg + 4]);
                af[mi][3] = __float_as_uint(A[(r0 + 8) * GA_PITCH + ks * 8 + tg + 4]);
            }
            #pragma unroll
            for (int ni = 0; ni < 8; ni++) {
                int col = wn * 64 + ni * 8 + g;
                uint32_t bf[2];
                bf[0] = __float_as_uint(Bt[(ks * 8 + tg) * GB_PITCH + col]);
                bf[1] = __float_as_uint(Bt[(ks * 8 + tg + 4) * GB_PITCH + col]);
                mma_tf32(acc[0][ni], af[0], bf);
                mma_tf32(acc[1][ni], af[1], bf);
            }
        }
        __syncthreads();
    }

    #pragma unroll
    for (int mi = 0; mi < 2; mi++) {
        #pragma unroll
        for (int ni = 0; ni < 8; ni++) {
            #pragma unroll
            for (int j = 0; j < 4; j++) {
                int r = wm * 32 + mi * 16 + g + ((j >= 2) ? 8 : 0);
                int c = wn * 64 + ni * 8 + tg * 2 + (j & 1);
                int m = m0 + r, n = n0 + c;
                int b = m >> 11, tok = m & 2047;
                float v = acc[mi][ni][j];
                if (n < QKDIM) {
                    v = tfround(v + bq[n]);
                    int h = n >> 6, d = n & 63;
                    g_Q[(((size_t)(b * NH + h)) * NTOK + tok) * HD + d] = v;
                } else if (n < 2 * QKDIM) {
                    int n2 = n - QKDIM;
                    v = tfround(v + bk[n2]);
                    int h = n2 >> 6, d = n2 & 63;
                    g_K[(((size_t)(b * NH + h)) * NTOK + tok) * HD + d] = v;
                } else {
                    int n2 = n - 2 * QKDIM;
                    v = tfround(v + bv[n2]);
                    int h = n2 >> 7, vd = n2 & 127;
                    g_V[(((size_t)(b * NH + h)) * NTOK + tok) * VD + vd] = v;
                }
            }
        }
    }
}

// ================================================================ Attention
// Br=64, Bc=64, 128 threads, warps tiled 2m x 2n (R12, +14us verified).
// NEW: K double-buffered -> the S->softmax barrier is gone (3 syncs/tile,
// was 4) and the K-prefetch instruction burst moves off the critical path.
// P + 2xK + V = 87 KB smem, 2 CTAs/SM. No max-subtraction softmax.
// Pipeline ledger (commit order): [Q][K0][V0][K1] ; per tile t (buf=t&1):
//   top:  wait_group 2  -> K(t) landed (V(t), K(t+1) may pend); sync
//   S(t) from K[buf]; exp -> P (no barrier between: K buffer not reused)
//   mid:  wait_group (t+2<TT ? 1 : 0) -> V(t) landed; sync (P done, S readers done)
//   P@V(t); end sync (V+P readers done)
//   loadV(t+1); loadK(t+2) into buf  [overwrite safe: S(t) fenced at mid]
#define QP 68     // 68 mod 32 = 4 -> Q/K/P frag reads bank 4g+tg = lane (CF)
#define VP 136    // 136 mod 32 = 8 -> V frag reads bank 8tg+g = perm(lane) (CF)
#define P_FLOATS (64 * QP)
#define K_STAGE  (64 * QP)
#define V_FLOATS (64 * VP)
#define ATT_SMEM_BYTES ((P_FLOATS + 2 * K_STAGE + V_FLOATS) * 4)   // 87040

__global__ __launch_bounds__(128, 2)
void attn_kernel(float* __restrict__ out)
{
    extern __shared__ float sm[];
    float* Ps = sm;                       // [64][QP]  (Q staging, then P)
    float* Ks = sm + P_FLOATS;            // [2][64][QP]
    float* Vs = Ks + 2 * K_STAGE;         // [64][VP]

    const int tid = threadIdx.x;
    const int qt = blockIdx.x;            // 0..31
    const int bh = blockIdx.y;            // 0..31
    const int b = bh >> 3, h = bh & 7;

    const float* Qg = g_Q + ((size_t)bh * NTOK + qt * 64) * HD;
    const float* Kg = g_K + (size_t)bh * NTOK * HD;
    const float* Vg = g_V + (size_t)bh * NTOK * VD;

    const uint32_t ps_b = smem_u32(Ps);
    const uint32_t ks_b = smem_u32(Ks);
    const uint32_t vs_b = smem_u32(Vs);

    // Stage Q into Ps                                         [group 0: Q]
    #pragma unroll
    for (int i = 0; i < 8; i++) {
        int idx = tid + 128 * i;
        int r = idx >> 4, c4 = idx & 15;
        cp16(ps_b + (uint32_t)(r * QP + c4 * 4) * 4, Qg + (size_t)r * HD + c4 * 4);
    }
    cp_commit();

    auto loadK = [&](int t) {             // into buffer t&1
        const float* Kt = Kg + (size_t)t * 64 * HD;
        uint32_t base = ks_b + (uint32_t)((t & 1) * K_STAGE) * 4;
        #pragma unroll
        for (int i = 0; i < 8; i++) {
            int idx = tid + 128 * i;
            int r = idx >> 4, c4 = idx & 15;
            cp16(base + (uint32_t)(r * QP + c4 * 4) * 4, Kt + (size_t)r * HD + c4 * 4);
        }
        cp_commit();
    };
    auto loadV = [&](int t) {
        const float* Vt = Vg + (size_t)t * 64 * VD;
        #pragma unroll
        for (int i = 0; i < 16; i++) {
            int idx = tid + 128 * i;
            int r = idx >> 5, c4 = idx & 31;
            cp16(vs_b + (uint32_t)(r * VP + c4 * 4) * 4, Vt + (size_t)r * VD + c4 * 4);
        }
        cp_commit();
    };

    loadK(0);          // group 1
    loadV(0);          // group 2
    loadK(1);          // group 3

    const int wid = tid >> 5, lane = tid & 31;
    const int g = lane >> 2, tg = lane & 3;
    const int wm = wid & 1, wn = wid >> 1;
    const int r0 = wm * 32;               // warp q-row base
    const int kc = wn * 32;               // warp S key-column base
    const int vc = wn * 64;               // warp P@V v-column base

    // Q fragments -> registers (wait Q only; K0,V0,K1 in flight)
    asm volatile("cp.async.wait_group 3;");
    __syncthreads();
    uint32_t aq[2][8][4];
    #pragma unroll
    for (int mi = 0; mi < 2; mi++) {
        int rr = r0 + mi * 16 + g;
        #pragma unroll
        for (int ks = 0; ks < 8; ks++) {
            aq[mi][ks][0] = __float_as_uint(Ps[rr * QP + ks * 8 + tg]);
            aq[mi][ks][1] = __float_as_uint(Ps[(rr + 8) * QP + ks * 8 + tg]);
            aq[mi][ks][2] = __float_as_uint(Ps[rr * QP + ks * 8 + tg + 4]);
            aq[mi][ks][3] = __float_as_uint(Ps[(rr + 8) * QP + ks * 8 + tg + 4]);
        }
    }
    // (top sync of tile 0 orders all aq reads before first P writes)

    float oacc[2][8][4];
    #pragma unroll
    for (int mi = 0; mi < 2; mi++)
        #pragma unroll
        for (int ni = 0; ni < 8; ni++)
            #pragma unroll
            for (int j = 0; j < 4; j++) oacc[mi][ni][j] = 0.f;
    float rs[2][2] = {{0.f, 0.f}, {0.f, 0.f}};

    const int TT = NTOK / 64;   // 32
    for (int t = 0; t < TT; t++) {
        const float* Kt = Ks + (t & 1) * K_STAGE;

        // top: K(t) landed (V(t), K(t+1) may stay pending)
        asm volatile("cp.async.wait_group 2;");
        __syncthreads();

        // ---- S = Q @ K^T  (warp: 32 rows x 32 keys) ----
        float s[2][4][4];
        #pragma unroll
        for (int mi = 0; mi < 2; mi++)
            #pragma unroll
            for (int ni = 0; ni < 4; ni++)
                #pragma unroll
                for (int j = 0; j < 4; j++) s[mi][ni][j] = 0.f;

        #pragma unroll
        for (int ks = 0; ks < 8; ks++) {
            #pragma unroll
            for (int ni = 0; ni < 4; ni++) {
                uint32_t bf[2];
                bf[0] = __float_as_uint(Kt[(kc + ni * 8 + g) * QP + ks * 8 + tg]);
                bf[1] = __float_as_uint(Kt[(kc + ni * 8 + g) * QP + ks * 8 + tg + 4]);
                mma_tf32(s[0][ni], aq[0][ks], bf);
                mma_tf32(s[1][ni], aq[1][ks], bf);
            }
        }

        // ---- exp + per-lane partial row sums; stage P quadrant ----
        // (no barrier after S: K buffer is double-buffered)
        #pragma unroll
        for (int mi = 0; mi < 2; mi++) {
            int rr = r0 + mi * 16 + g;
            #pragma unroll
            for (int ni = 0; ni < 4; ni++) {
                float e0 = __expf(s[mi][ni][0] * ATT_SCALE);
                float e1 = __expf(s[mi][ni][1] * ATT_SCALE);
                float e2 = __expf(s[mi][ni][2] * ATT_SCALE);
                float e3 = __expf(s[mi][ni][3] * ATT_SCALE);
                rs[mi][0] += e0 + e1;
                rs[mi][1] += e2 + e3;
                Ps[rr * QP + kc + ni * 8 + tg * 2]           = tfround(e0);
                Ps[rr * QP + kc + ni * 8 + tg * 2 + 1]       = tfround(e1);
                Ps[(rr + 8) * QP + kc + ni * 8 + tg * 2]     = tfround(e2);
                Ps[(rr + 8) * QP + kc + ni * 8 + tg * 2 + 1] = tfround(e3);
            }
        }

        // mid: V(t) landed (K(t+1) may pend; tail over-waits harmlessly)
        if (t + 2 < TT) { asm volatile("cp.async.wait_group 1;"); }
        else            { asm volatile("cp.async.wait_group 0;"); }
        __syncthreads();   // P complete + V ready + S readers of K buf done

        // ---- O += P @ V  (warp: 32 rows x 64 v-cols, k = 64 keys) ----
        #pragma unroll
        for (int ks = 0; ks < 8; ks++) {
            uint32_t af[2][4];
            #pragma unroll
            for (int mi = 0; mi < 2; mi++) {
                int rr = r0 + mi * 16 + g;
                af[mi][0] = __float_as_uint(Ps[rr * QP + ks * 8 + tg]);
                af[mi][1] = __float_as_uint(Ps[(rr + 8) * QP + ks * 8 + tg]);
                af[mi][2] = __float_as_uint(Ps[rr * QP + ks * 8 + tg + 4]);
                af[mi][3] = __float_as_uint(Ps[(rr + 8) * QP + ks * 8 + tg + 4]);
            }
            #pragma unroll
            for (int ni = 0; ni < 8; ni++) {
                uint32_t bf[2];
                bf[0] = __float_as_uint(Vs[(ks * 8 + tg) * VP + vc + ni * 8 + g]);
                bf[1] = __float_as_uint(Vs[(ks * 8 + tg + 4) * VP + vc + ni * 8 + g]);
                mma_tf32(oacc[0][ni], af[0], bf);
                mma_tf32(oacc[1][ni], af[1], bf);
            }
        }

        __syncthreads();                 // end: V + P readers done
        if (t + 1 < TT) loadV(t + 1);
        if (t + 2 < TT) loadK(t + 2);    // into buf t&1 (S(t) fenced at mid)
    }

    // ---- epilogue: row-sum reduction (intra-warp, then cross-warp via smem) ----
    #pragma unroll
    for (int mi = 0; mi < 2; mi++)
        #pragma unroll
        for (int hf = 0; hf < 2; hf++) {
            float v = rs[mi][hf];
            v += __shfl_xor_sync(0xffffffffu, v, 1);
            v += __shfl_xor_sync(0xffffffffu, v, 2);
            rs[mi][hf] = v;
        }
    float* RS = Ps;                      // Ps free after last end-sync
    if (tg == 0) {
        #pragma unroll
        for (int mi = 0; mi < 2; mi++)
            #pragma unroll
            for (int hf = 0; hf < 2; hf++)
                RS[wn * 64 + r0 + mi * 16 + hf * 8 + g] = rs[mi][hf];
    }
    __syncthreads();

    #pragma unroll
    for (int mi = 0; mi < 2; mi++) {
        int rr = r0 + mi * 16 + g;
        float inv0 = 1.f / (RS[rr] + RS[64 + rr]);
        float inv1 = 1.f / (RS[rr + 8] + RS[64 + rr + 8]);
        int tokA = qt * 64 + rr;
        float* op = out + ((size_t)b * NTOK + tokA) * OUTCH + (size_t)h * VD + vc;
        #pragma unroll
        for (int ni = 0; ni < 8; ni++) {
            int c = ni * 8 + tg * 2;
            op[c]                  = oacc[mi][ni][0] * inv0;
            op[c + 1]              = oacc[mi][ni][1] * inv0;
            op[8 * OUTCH + c]      = oacc[mi][ni][2] * inv1;
            op[8 * OUTCH + c + 1]  = oacc[mi][ni][3] * inv1;
        }
    }
}

// ================================================================ launch
extern "C" void kernel_launch(void* const* d_in, const int* in_sizes, int n_in,
                              void* d_out, int out_size)
{
    const float* x  = (const float*)d_in[0];
    const float* Wq = (const float*)d_in[1];
    const float* bq = (const float*)d_in[2];
    const float* Wk = (const float*)d_in[3];
    const float* bk = (const float*)d_in[4];
    const float* Wv = (const float*)d_in[5];
    const float* bv = (const float*)d_in[6];
    float* out = (float*)d_out;

    cudaFuncSetAttribute(qkv_gemm, cudaFuncAttributeMaxDynamicSharedMemorySize,
                         GEMM_SMEM_BYTES);
    cudaFuncSetAttribute(attn_kernel, cudaFuncAttributeMaxDynamicSharedMemorySize,
                         ATT_SMEM_BYTES);

    preround_x<<<2048, 256>>>((const float4*)x);                         // idx 0
    preround_w<<<1024, 256>>>((const float4*)Wq, (const float4*)Wk,
                              (const float4*)Wv);                        // idx 1
    dim3 g1(OUTCH * 2 / 128, (NB * NTOK) / 128);
    qkv_gemm<<<g1, 256, GEMM_SMEM_BYTES>>>(bq, bk, bv);                  // idx 2
    dim3 g2(NTOK / 64, NB * NH);
    attn_kernel<<<g2, 128, ATT_SMEM_BYTES>>>(out);                       // idx 3 -> profiled
}

// round 15
// speedup vs baseline: 1.0783x; 1.0486x over previous
#include <cuda_runtime.h>
#include <cstdint>
#include <cstddef>

// Problem constants
#define NB    4
#define NTOK  2048
#define CIN   1024
#define QKDIM 512
#define OUTCH 1024
#define NH    8
#define HD    64     // per-head qk dim
#define VD    128    // per-head value dim
// exp(s*0.125) = ex2(s * 0.125*log2(e))
#define SC_LOG2E 0.18033688011112042f

// Scratch (static device globals)
static __device__ float g_Q[(size_t)NB * NH * NTOK * HD];   // [bh][tok][d]  tf32
static __device__ float g_K[(size_t)NB * NH * NTOK * HD];   // [bh][tok][d]  tf32
static __device__ float g_V[(size_t)NB * NH * NTOK * VD];   // [bh][tok][v]  tf32
static __device__ float g_Xr[(size_t)NB * NTOK * CIN];      // tf32-rounded X
static __device__ float g_Wqr[(size_t)CIN * QKDIM];
static __device__ float g_Wkr[(size_t)CIN * QKDIM];
static __device__ float g_Wvr[(size_t)CIN * OUTCH];

// ---------------------------------------------------------------- helpers
__device__ __forceinline__ uint32_t f2tf(float x) {
    uint32_t u;
    asm("cvt.rna.tf32.f32 %0, %1;" : "=r"(u) : "f"(x));
    return u;
}
__device__ __forceinline__ float tfround(float x) { return __uint_as_float(f2tf(x)); }
// What HMMA.TF32 actually sees when fed raw fp32 bits: mantissa truncated to 10 bits.
__device__ __forceinline__ float tftrunc(float x) {
    return __uint_as_float(__float_as_uint(x) & 0xffffe000u);
}
__device__ __forceinline__ float ex2(float x) {
    float r;
    asm("ex2.approx.f32 %0, %1;" : "=f"(r) : "f"(x));
    return r;
}
__device__ __forceinline__ void mma_tf32(float c[4], const uint32_t a[4], const uint32_t b[2]) {
    asm volatile(
        "mma.sync.aligned.m16n8k8.row.col.f32.tf32.tf32.f32 "
        "{%0,%1,%2,%3},{%4,%5,%6,%7},{%8,%9},{%0,%1,%2,%3};"
        : "+f"(c[0]), "+f"(c[1]), "+f"(c[2]), "+f"(c[3])
        : "r"(a[0]), "r"(a[1]), "r"(a[2]), "r"(a[3]), "r"(b[0]), "r"(b[1]));
}
__device__ __forceinline__ uint32_t smem_u32(const void* p) {
    return (uint32_t)__cvta_generic_to_shared(p);
}
__device__ __forceinline__ void cp16(uint32_t dst, const void* src) {
    asm volatile("cp.async.cg.shared.global [%0], [%1], 16;" :: "r"(dst), "l"(src));
}
__device__ __forceinline__ void cp_commit() { asm volatile("cp.async.commit_group;"); }

// ================================================================ Pre-round X  (launch idx 0)
#define NX4  ((NB * NTOK * CIN) / 4)
__global__ __launch_bounds__(256)
void preround_x(const float4* __restrict__ X)
{
    for (size_t i = (size_t)blockIdx.x * blockDim.x + threadIdx.x;
         i < NX4; i += (size_t)gridDim.x * blockDim.x) {
        float4 v = X[i];
        v.x = tfround(v.x); v.y = tfround(v.y); v.z = tfround(v.z); v.w = tfround(v.w);
        ((float4*)g_Xr)[i] = v;
    }
}

// ================================================================ Pre-round W  (launch idx 1)
#define NQ4  ((CIN * QKDIM) / 4)
#define NV4  ((CIN * OUTCH) / 4)
#define NW4  (2 * NQ4 + NV4)
__global__ __launch_bounds__(256)
void preround_w(const float4* __restrict__ Wq, const float4* __restrict__ Wk,
                const float4* __restrict__ Wv)
{
    for (size_t i = (size_t)blockIdx.x * blockDim.x + threadIdx.x;
         i < NW4; i += (size_t)gridDim.x * blockDim.x) {
        float4 v; float4* dst;
        if (i < NQ4)            { v = Wq[i];           dst = ((float4*)g_Wqr) + i; }
        else if (i < 2 * NQ4)   { v = Wk[i - NQ4];     dst = ((float4*)g_Wkr) + (i - NQ4); }
        else                    { v = Wv[i - 2 * NQ4]; dst = ((float4*)g_Wvr) + (i - 2 * NQ4); }
        v.x = tfround(v.x); v.y = tfround(v.y); v.z = tfround(v.z); v.w = tfround(v.w);
        *dst = v;
    }
}

// ================================================================ QKV GEMM
// NEW: force 2 CTAs/SM (regs capped at 128; est. need ~110). 16 warps/SM.
#define GA_PITCH 36
#define GB_PITCH 136
#define GA_STAGE (128 * GA_PITCH)
#define GB_STAGE (32 * GB_PITCH)
#define GEMM_SMEM_BYTES ((2 * GA_STAGE + 2 * GB_STAGE) * 4)

__global__ __launch_bounds__(256, 2)
void qkv_gemm(const float* __restrict__ bq, const float* __restrict__ bk,
              const float* __restrict__ bv)
{
    extern __shared__ float sm[];
    float* As = sm;
    float* Bs = sm + 2 * GA_STAGE;

    const int tid = threadIdx.x;
    const int m0 = blockIdx.y * 128;
    const int n0 = blockIdx.x * 128;

    const float* Wsrc;
    int wld, nc0;
    if (n0 < QKDIM)          { Wsrc = g_Wqr; wld = QKDIM; nc0 = n0;            }
    else if (n0 < 2 * QKDIM) { Wsrc = g_Wkr; wld = QKDIM; nc0 = n0 - QKDIM;    }
    else                     { Wsrc = g_Wvr; wld = OUTCH; nc0 = n0 - 2*QKDIM;  }

    const uint32_t as_b = smem_u32(As);
    const uint32_t bs_b = smem_u32(Bs);

    auto load_stage = [&](int stage, int k0) {
        #pragma unroll
        for (int i = 0; i < 4; i++) {
            int idx = tid + 256 * i;
            int r = idx >> 3, c4 = idx & 7;
            cp16(as_b + (uint32_t)(stage * GA_STAGE + r * GA_PITCH + c4 * 4) * 4,
                 g_Xr + (size_t)(m0 + r) * CIN + k0 + c4 * 4);
        }
        #pragma unroll
        for (int i = 0; i < 4; i++) {
            int idx = tid + 256 * i;
            int r = idx >> 5, c4 = idx & 31;
            cp16(bs_b + (uint32_t)(stage * GB_STAGE + r * GB_PITCH + c4 * 4) * 4,
                 Wsrc + (size_t)(k0 + r) * wld + nc0 + c4 * 4);
        }
        cp_commit();
    };

    const int wid = tid >> 5, lane = tid & 31;
    const int wm = wid & 3, wn = wid >> 2;
    const int g = lane >> 2, tg = lane & 3;

    float acc[2][8][4];
    #pragma unroll
    for (int mi = 0; mi < 2; mi++)
        #pragma unroll
        for (int ni = 0; ni < 8; ni++)
            #pragma unroll
            for (int j = 0; j < 4; j++) acc[mi][ni][j] = 0.f;

    load_stage(0, 0);

    const int KT = CIN / 32;
    for (int kt = 0; kt < KT; kt++) {
        if (kt + 1 < KT) {
            load_stage((kt + 1) & 1, (kt + 1) * 32);
            asm volatile("cp.async.wait_group 1;");
        } else {
            asm volatile("cp.async.wait_group 0;");
        }
        __syncthreads();

        const float* A  = As + (kt & 1) * GA_STAGE;
        const float* Bt = Bs + (kt & 1) * GB_STAGE;

        #pragma unroll
        for (int ks = 0; ks < 4; ks++) {
            uint32_t af[2][4];
            #pragma unroll
            for (int mi = 0; mi < 2; mi++) {
                int r0 = wm * 32 + mi * 16 + g;
                af[mi][0] = __float_as_uint(A[r0 * GA_PITCH + ks * 8 + tg]);
                af[mi][1] = __float_as_uint(A[(r0 + 8) * GA_PITCH + ks * 8 + tg]);
                af[mi][2] = __float_as_uint(A[r0 * GA_PITCH + ks * 8 + tg + 4]);
                af[mi][3] = __float_as_uint(A[(r0 + 8) * GA_PITCH + ks * 8 + tg + 4]);
            }
            #pragma unroll
            for (int ni = 0; ni < 8; ni++) {
                int col = wn * 64 + ni * 8 + g;
                uint32_t bf[2];
                bf[0] = __float_as_uint(Bt[(ks * 8 + tg) * GB_PITCH + col]);
                bf[1] = __float_as_uint(Bt[(ks * 8 + tg + 4) * GB_PITCH + col]);
                mma_tf32(acc[0][ni], af[0], bf);
                mma_tf32(acc[1][ni], af[1], bf);
            }
        }
        __syncthreads();
    }

    #pragma unroll
    for (int mi = 0; mi < 2; mi++) {
        #pragma unroll
        for (int ni = 0; ni < 8; ni++) {
            #pragma unroll
            for (int j = 0; j < 4; j++) {
                int r = wm * 32 + mi * 16 + g + ((j >= 2) ? 8 : 0);
                int c = wn * 64 + ni * 8 + tg * 2 + (j & 1);
                int m = m0 + r, n = n0 + c;
                int b = m >> 11, tok = m & 2047;
                float v = acc[mi][ni][j];
                if (n < QKDIM) {
                    v = tfround(v + bq[n]);
                    int h = n >> 6, d = n & 63;
                    g_Q[(((size_t)(b * NH + h)) * NTOK + tok) * HD + d] = v;
                } else if (n < 2 * QKDIM) {
                    int n2 = n - QKDIM;
                    v = tfround(v + bk[n2]);
                    int h = n2 >> 6, d = n2 & 63;
                    g_K[(((size_t)(b * NH + h)) * NTOK + tok) * HD + d] = v;
                } else {
                    int n2 = n - 2 * QKDIM;
                    v = tfround(v + bv[n2]);
                    int h = n2 >> 7, vd = n2 & 127;
                    g_V[(((size_t)(b * NH + h)) * NTOK + tok) * VD + vd] = v;
                }
            }
        }
    }
}

// ================================================================ Attention
// R13 structure (2m x 2n warps, K double-buffered, 3 syncs/tile) with the
// softmax chain shortened: P stored as RAW fp32 (HMMA truncates mantissa in
// HW), rsum accumulates the same truncated values (bias-matched numerator /
// denominator), exp folded to a single FMUL + MUFU ex2.
#define QP 68     // 68 mod 32 = 4 -> Q/K/P frag reads bank 4g+tg = lane (CF)
#define VP 136    // 136 mod 32 = 8 -> V frag reads bank 8tg+g = perm(lane) (CF)
#define P_FLOATS (64 * QP)
#define K_STAGE  (64 * QP)
#define V_FLOATS (64 * VP)
#define ATT_SMEM_BYTES ((P_FLOATS + 2 * K_STAGE + V_FLOATS) * 4)   // 87040

__global__ __launch_bounds__(128, 2)
void attn_kernel(float* __restrict__ out)
{
    extern __shared__ float sm[];
    float* Ps = sm;                       // [64][QP]  (Q staging, then P)
    float* Ks = sm + P_FLOATS;            // [2][64][QP]
    float* Vs = Ks + 2 * K_STAGE;         // [64][VP]

    const int tid = threadIdx.x;
    const int qt = blockIdx.x;            // 0..31
    const int bh = blockIdx.y;            // 0..31
    const int b = bh >> 3, h = bh & 7;

    const float* Qg = g_Q + ((size_t)bh * NTOK + qt * 64) * HD;
    const float* Kg = g_K + (size_t)bh * NTOK * HD;
    const float* Vg = g_V + (size_t)bh * NTOK * VD;

    const uint32_t ps_b = smem_u32(Ps);
    const uint32_t ks_b = smem_u32(Ks);
    const uint32_t vs_b = smem_u32(Vs);

    // Stage Q into Ps                                         [group 0: Q]
    #pragma unroll
    for (int i = 0; i < 8; i++) {
        int idx = tid + 128 * i;
        int r = idx >> 4, c4 = idx & 15;
        cp16(ps_b + (uint32_t)(r * QP + c4 * 4) * 4, Qg + (size_t)r * HD + c4 * 4);
    }
    cp_commit();

    auto loadK = [&](int t) {             // into buffer t&1
        const float* Kt = Kg + (size_t)t * 64 * HD;
        uint32_t base = ks_b + (uint32_t)((t & 1) * K_STAGE) * 4;
        #pragma unroll
        for (int i = 0; i < 8; i++) {
            int idx = tid + 128 * i;
            int r = idx >> 4, c4 = idx & 15;
            cp16(base + (uint32_t)(r * QP + c4 * 4) * 4, Kt + (size_t)r * HD + c4 * 4);
        }
        cp_commit();
    };
    auto loadV = [&](int t) {
        const float* Vt = Vg + (size_t)t * 64 * VD;
        #pragma unroll
        for (int i = 0; i < 16; i++) {
            int idx = tid + 128 * i;
            int r = idx >> 5, c4 = idx & 31;
            cp16(vs_b + (uint32_t)(r * VP + c4 * 4) * 4, Vt + (size_t)r * VD + c4 * 4);
        }
        cp_commit();
    };

    loadK(0);          // group 1
    loadV(0);          // group 2
    loadK(1);          // group 3

    const int wid = tid >> 5, lane = tid & 31;
    const int g = lane >> 2, tg = lane & 3;
    const int wm = wid & 1, wn = wid >> 1;
    const int r0 = wm * 32;               // warp q-row base
    const int kc = wn * 32;               // warp S key-column base
    const int vc = wn * 64;               // warp P@V v-column base

    // Q fragments -> registers (wait Q only; K0,V0,K1 in flight)
    asm volatile("cp.async.wait_group 3;");
    __syncthreads();
    uint32_t aq[2][8][4];
    #pragma unroll
    for (int mi = 0; mi < 2; mi++) {
        int rr = r0 + mi * 16 + g;
        #pragma unroll
        for (int ks = 0; ks < 8; ks++) {
            aq[mi][ks][0] = __float_as_uint(Ps[rr * QP + ks * 8 + tg]);
            aq[mi][ks][1] = __float_as_uint(Ps[(rr + 8) * QP + ks * 8 + tg]);
            aq[mi][ks][2] = __float_as_uint(Ps[rr * QP + ks * 8 + tg + 4]);
            aq[mi][ks][3] = __float_as_uint(Ps[(rr + 8) * QP + ks * 8 + tg + 4]);
        }
    }

    float oacc[2][8][4];
    #pragma unroll
    for (int mi = 0; mi < 2; mi++)
        #pragma unroll
        for (int ni = 0; ni < 8; ni++)
            #pragma unroll
            for (int j = 0; j < 4; j++) oacc[mi][ni][j] = 0.f;
    float rs[2][2] = {{0.f, 0.f}, {0.f, 0.f}};

    const int TT = NTOK / 64;   // 32
    for (int t = 0; t < TT; t++) {
        const float* Kt = Ks + (t & 1) * K_STAGE;

        // top: K(t) landed (V(t), K(t+1) may stay pending)
        asm volatile("cp.async.wait_group 2;");
        __syncthreads();

        // ---- S = Q @ K^T  (warp: 32 rows x 32 keys) ----
        float s[2][4][4];
        #pragma unroll
        for (int mi = 0; mi < 2; mi++)
            #pragma unroll
            for (int ni = 0; ni < 4; ni++)
                #pragma unroll
                for (int j = 0; j < 4; j++) s[mi][ni][j] = 0.f;

        #pragma unroll
        for (int ks = 0; ks < 8; ks++) {
            #pragma unroll
            for (int ni = 0; ni < 4; ni++) {
                uint32_t bf[2];
                bf[0] = __float_as_uint(Kt[(kc + ni * 8 + g) * QP + ks * 8 + tg]);
                bf[1] = __float_as_uint(Kt[(kc + ni * 8 + g) * QP + ks * 8 + tg + 4]);
                mma_tf32(s[0][ni], aq[0][ks], bf);
                mma_tf32(s[1][ni], aq[1][ks], bf);
            }
        }

        // ---- exp (1 FMUL + MUFU); raw P to smem; truncated values to rsum ----
        #pragma unroll
        for (int mi = 0; mi < 2; mi++) {
            int rr = r0 + mi * 16 + g;
            #pragma unroll
            for (int ni = 0; ni < 4; ni++) {
                float e0 = ex2(s[mi][ni][0] * SC_LOG2E);
                float e1 = ex2(s[mi][ni][1] * SC_LOG2E);
                float e2 = ex2(s[mi][ni][2] * SC_LOG2E);
                float e3 = ex2(s[mi][ni][3] * SC_LOG2E);
                Ps[rr * QP + kc + ni * 8 + tg * 2]           = e0;
                Ps[rr * QP + kc + ni * 8 + tg * 2 + 1]       = e1;
                Ps[(rr + 8) * QP + kc + ni * 8 + tg * 2]     = e2;
                Ps[(rr + 8) * QP + kc + ni * 8 + tg * 2 + 1] = e3;
                // rsum must see exactly what HMMA sees: truncated mantissa
                rs[mi][0] += tftrunc(e0) + tftrunc(e1);
                rs[mi][1] += tftrunc(e2) + tftrunc(e3);
            }
        }

        // mid: V(t) landed (K(t+1) may pend; tail over-waits harmlessly)
        if (t + 2 < TT) { asm volatile("cp.async.wait_group 1;"); }
        else            { asm volatile("cp.async.wait_group 0;"); }
        __syncthreads();   // P complete + V ready + S readers of K buf done

        // ---- O += P @ V  (warp: 32 rows x 64 v-cols, k = 64 keys) ----
        #pragma unroll
        for (int ks = 0; ks < 8; ks++) {
            uint32_t af[2][4];
            #pragma unroll
            for (int mi = 0; mi < 2; mi++) {
                int rr = r0 + mi * 16 + g;
                af[mi][0] = __float_as_uint(Ps[rr * QP + ks * 8 + tg]);
                af[mi][1] = __float_as_uint(Ps[(rr + 8) * QP + ks * 8 + tg]);
                af[mi][2] = __float_as_uint(Ps[rr * QP + ks * 8 + tg + 4]);
                af[mi][3] = __float_as_uint(Ps[(rr + 8) * QP + ks * 8 + tg + 4]);
            }
            #pragma unroll
            for (int ni = 0; ni < 8; ni++) {
                uint32_t bf[2];
                bf[0] = __float_as_uint(Vs[(ks * 8 + tg) * VP + vc + ni * 8 + g]);
                bf[1] = __float_as_uint(Vs[(ks * 8 + tg + 4) * VP + vc + ni * 8 + g]);
                mma_tf32(oacc[0][ni], af[0], bf);
                mma_tf32(oacc[1][ni], af[1], bf);
            }
        }

        __syncthreads();                 // end: V + P readers done
        if (t + 1 < TT) loadV(t + 1);
        if (t + 2 < TT) loadK(t + 2);    // into buf t&1 (S(t) fenced at mid)
    }

    // ---- epilogue: row-sum reduction (intra-warp, then cross-warp via smem) ----
    #pragma unroll
    for (int mi = 0; mi < 2; mi++)
        #pragma unroll
        for (int hf = 0; hf < 2; hf++) {
            float v = rs[mi][hf];
            v += __shfl_xor_sync(0xffffffffu, v, 1);
            v += __shfl_xor_sync(0xffffffffu, v, 2);
            rs[mi][hf] = v;
        }
    float* RS = Ps;                      // Ps free after last end-sync
    if (tg == 0) {
        #pragma unroll
        for (int mi = 0; mi < 2; mi++)
            #pragma unroll
            for (int hf = 0; hf < 2; hf++)
                RS[wn * 64 + r0 + mi * 16 + hf * 8 + g] = rs[mi][hf];
    }
    __syncthreads();

    #pragma unroll
    for (int mi = 0; mi < 2; mi++) {
        int rr = r0 + mi * 16 + g;
        float inv0 = 1.f / (RS[rr] + RS[64 + rr]);
        float inv1 = 1.f / (RS[rr + 8] + RS[64 + rr + 8]);
        int tokA = qt * 64 + rr;
        float* op = out + ((size_t)b * NTOK + tokA) * OUTCH + (size_t)h * VD + vc;
        #pragma unroll
        for (int ni = 0; ni < 8; ni++) {
            int c = ni * 8 + tg * 2;
            op[c]                  = oacc[mi][ni][0] * inv0;
            op[c + 1]              = oacc[mi][ni][1] * inv0;
            op[8 * OUTCH + c]      = oacc[mi][ni][2] * inv1;
            op[8 * OUTCH + c + 1]  = oacc[mi][ni][3] * inv1;
        }
    }
}

// ================================================================ launch
extern "C" void kernel_launch(void* const* d_in, const int* in_sizes, int n_in,
                              void* d_out, int out_size)
{
    const float* x  = (const float*)d_in[0];
    const float* Wq = (const float*)d_in[1];
    const float* bq = (const float*)d_in[2];
    const float* Wk = (const float*)d_in[3];
    const float* bk = (const float*)d_in[4];
    const float* Wv = (const float*)d_in[5];
    const float* bv = (const float*)d_in[6];
    float* out = (float*)d_out;

    cudaFuncSetAttribute(qkv_gemm, cudaFuncAttributeMaxDynamicSharedMemorySize,
                         GEMM_SMEM_BYTES);
    cudaFuncSetAttribute(attn_kernel, cudaFuncAttributeMaxDynamicSharedMemorySize,
                         ATT_SMEM_BYTES);

    preround_x<<<2048, 256>>>((const float4*)x);                         // idx 0
    preround_w<<<1024, 256>>>((const float4*)Wq, (const float4*)Wk,
                              (const float4*)Wv);                        // idx 1
    dim3 g1(OUTCH * 2 / 128, (NB * NTOK) / 128);
    qkv_gemm<<<g1, 256, GEMM_SMEM_BYTES>>>(bq, bk, bv);                  // idx 2
    dim3 g2(NTOK / 64, NB * NH);
    attn_kernel<<<g2, 128, ATT_SMEM_BYTES>>>(out);                       // idx 3 -> profiled
}

// round 16
// speedup vs baseline: 1.1032x; 1.0231x over previous
#include <cuda_runtime.h>
#include <cstdint>
#include <cstddef>

// Problem constants
#define NB    4
#define NTOK  2048
#define CIN   1024
#define QKDIM 512
#define OUTCH 1024
#define NH    8
#define HD    64     // per-head qk dim
#define VD    128    // per-head value dim
// exp(s*0.125) = ex2(s * 0.125*log2(e))
#define SC_LOG2E 0.18033688011112042f

// Scratch (static device globals)
static __device__ float g_Q[(size_t)NB * NH * NTOK * HD];   // [bh][tok][d]  tf32
static __device__ float g_K[(size_t)NB * NH * NTOK * HD];   // [bh][tok][d]  tf32
static __device__ float g_V[(size_t)NB * NH * NTOK * VD];   // [bh][tok][v]  tf32
static __device__ float g_Xr[(size_t)NB * NTOK * CIN];      // tf32-rounded X
static __device__ float g_Wqr[(size_t)CIN * QKDIM];
static __device__ float g_Wkr[(size_t)CIN * QKDIM];
static __device__ float g_Wvr[(size_t)CIN * OUTCH];

// ---------------------------------------------------------------- helpers
__device__ __forceinline__ uint32_t f2tf(float x) {
    uint32_t u;
    asm("cvt.rna.tf32.f32 %0, %1;" : "=r"(u) : "f"(x));
    return u;
}
__device__ __forceinline__ float tfround(float x) { return __uint_as_float(f2tf(x)); }
// What HMMA.TF32 sees when fed raw fp32 bits: mantissa truncated to 10 bits.
__device__ __forceinline__ float tftrunc(float x) {
    return __uint_as_float(__float_as_uint(x) & 0xffffe000u);
}
__device__ __forceinline__ float ex2(float x) {
    float r;
    asm("ex2.approx.f32 %0, %1;" : "=f"(r) : "f"(x));
    return r;
}
__device__ __forceinline__ void mma_tf32(float c[4], const uint32_t a[4], const uint32_t b[2]) {
    asm volatile(
        "mma.sync.aligned.m16n8k8.row.col.f32.tf32.tf32.f32 "
        "{%0,%1,%2,%3},{%4,%5,%6,%7},{%8,%9},{%0,%1,%2,%3};"
        : "+f"(c[0]), "+f"(c[1]), "+f"(c[2]), "+f"(c[3])
        : "r"(a[0]), "r"(a[1]), "r"(a[2]), "r"(a[3]), "r"(b[0]), "r"(b[1]));
}
__device__ __forceinline__ uint32_t smem_u32(const void* p) {
    return (uint32_t)__cvta_generic_to_shared(p);
}
__device__ __forceinline__ void cp16(uint32_t dst, const void* src) {
    asm volatile("cp.async.cg.shared.global [%0], [%1], 16;" :: "r"(dst), "l"(src));
}
__device__ __forceinline__ void cp_commit() { asm volatile("cp.async.commit_group;"); }

// ================================================================ Pre-round X  (launch idx 0)
#define NX4  ((NB * NTOK * CIN) / 4)
__global__ __launch_bounds__(256)
void preround_x(const float4* __restrict__ X)
{
    for (size_t i = (size_t)blockIdx.x * blockDim.x + threadIdx.x;
         i < NX4; i += (size_t)gridDim.x * blockDim.x) {
        float4 v = X[i];
        v.x = tfround(v.x); v.y = tfround(v.y); v.z = tfround(v.z); v.w = tfround(v.w);
        ((float4*)g_Xr)[i] = v;
    }
}

// ================================================================ Pre-round W  (launch idx 1)
#define NQ4  ((CIN * QKDIM) / 4)
#define NV4  ((CIN * OUTCH) / 4)
#define NW4  (2 * NQ4 + NV4)
__global__ __launch_bounds__(256)
void preround_w(const float4* __restrict__ Wq, const float4* __restrict__ Wk,
                const float4* __restrict__ Wv)
{
    for (size_t i = (size_t)blockIdx.x * blockDim.x + threadIdx.x;
         i < NW4; i += (size_t)gridDim.x * blockDim.x) {
        float4 v; float4* dst;
        if (i < NQ4)            { v = Wq[i];           dst = ((float4*)g_Wqr) + i; }
        else if (i < 2 * NQ4)   { v = Wk[i - NQ4];     dst = ((float4*)g_Wkr) + (i - NQ4); }
        else                    { v = Wv[i - 2 * NQ4]; dst = ((float4*)g_Wvr) + (i - 2 * NQ4); }
        v.x = tfround(v.x); v.y = tfround(v.y); v.z = tfround(v.z); v.w = tfround(v.w);
        *dst = v;
    }
}

// ================================================================ QKV GEMM (2 CTAs/SM, verified R15)
#define GA_PITCH 36
#define GB_PITCH 136
#define GA_STAGE (128 * GA_PITCH)
#define GB_STAGE (32 * GB_PITCH)
#define GEMM_SMEM_BYTES ((2 * GA_STAGE + 2 * GB_STAGE) * 4)

__global__ __launch_bounds__(256, 2)
void qkv_gemm(const float* __restrict__ bq, const float* __restrict__ bk,
              const float* __restrict__ bv)
{
    extern __shared__ float sm[];
    float* As = sm;
    float* Bs = sm + 2 * GA_STAGE;

    const int tid = threadIdx.x;
    const int m0 = blockIdx.y * 128;
    const int n0 = blockIdx.x * 128;

    const float* Wsrc;
    int wld, nc0;
    if (n0 < QKDIM)          { Wsrc = g_Wqr; wld = QKDIM; nc0 = n0;            }
    else if (n0 < 2 * QKDIM) { Wsrc = g_Wkr; wld = QKDIM; nc0 = n0 - QKDIM;    }
    else                     { Wsrc = g_Wvr; wld = OUTCH; nc0 = n0 - 2*QKDIM;  }

    const uint32_t as_b = smem_u32(As);
    const uint32_t bs_b = smem_u32(Bs);

    auto load_stage = [&](int stage, int k0) {
        #pragma unroll
        for (int i = 0; i < 4; i++) {
            int idx = tid + 256 * i;
            int r = idx >> 3, c4 = idx & 7;
            cp16(as_b + (uint32_t)(stage * GA_STAGE + r * GA_PITCH + c4 * 4) * 4,
                 g_Xr + (size_t)(m0 + r) * CIN + k0 + c4 * 4);
        }
        #pragma unroll
        for (int i = 0; i < 4; i++) {
            int idx = tid + 256 * i;
            int r = idx >> 5, c4 = idx & 31;
            cp16(bs_b + (uint32_t)(stage * GB_STAGE + r * GB_PITCH + c4 * 4) * 4,
                 Wsrc + (size_t)(k0 + r) * wld + nc0 + c4 * 4);
        }
        cp_commit();
    };

    const int wid = tid >> 5, lane = tid & 31;
    const int wm = wid & 3, wn = wid >> 2;
    const int g = lane >> 2, tg = lane & 3;

    float acc[2][8][4];
    #pragma unroll
    for (int mi = 0; mi < 2; mi++)
        #pragma unroll
        for (int ni = 0; ni < 8; ni++)
            #pragma unroll
            for (int j = 0; j < 4; j++) acc[mi][ni][j] = 0.f;

    load_stage(0, 0);

    const int KT = CIN / 32;
    for (int kt = 0; kt < KT; kt++) {
        if (kt + 1 < KT) {
            load_stage((kt + 1) & 1, (kt + 1) * 32);
            asm volatile("cp.async.wait_group 1;");
        } else {
            asm volatile("cp.async.wait_group 0;");
        }
        __syncthreads();

        const float* A  = As + (kt & 1) * GA_STAGE;
        const float* Bt = Bs + (kt & 1) * GB_STAGE;

        #pragma unroll
        for (int ks = 0; ks < 4; ks++) {
            uint32_t af[2][4];
            #pragma unroll
            for (int mi = 0; mi < 2; mi++) {
                int r0 = wm * 32 + mi * 16 + g;
                af[mi][0] = __float_as_uint(A[r0 * GA_PITCH + ks * 8 + tg]);
                af[mi][1] = __float_as_uint(A[(r0 + 8) * GA_PITCH + ks * 8 + tg]);
                af[mi][2] = __float_as_uint(A[r0 * GA_PITCH + ks * 8 + tg + 4]);
                af[mi][3] = __float_as_uint(A[(r0 + 8) * GA_PITCH + ks * 8 + tg + 4]);
            }
            #pragma unroll
            for (int ni = 0; ni < 8; ni++) {
                int col = wn * 64 + ni * 8 + g;
                uint32_t bf[2];
                bf[0] = __float_as_uint(Bt[(ks * 8 + tg) * GB_PITCH + col]);
                bf[1] = __float_as_uint(Bt[(ks * 8 + tg + 4) * GB_PITCH + col]);
                mma_tf32(acc[0][ni], af[0], bf);
                mma_tf32(acc[1][ni], af[1], bf);
            }
        }
        __syncthreads();
    }

    #pragma unroll
    for (int mi = 0; mi < 2; mi++) {
        #pragma unroll
        for (int ni = 0; ni < 8; ni++) {
            #pragma unroll
            for (int j = 0; j < 4; j++) {
                int r = wm * 32 + mi * 16 + g + ((j >= 2) ? 8 : 0);
                int c = wn * 64 + ni * 8 + tg * 2 + (j & 1);
                int m = m0 + r, n = n0 + c;
                int b = m >> 11, tok = m & 2047;
                float v = acc[mi][ni][j];
                if (n < QKDIM) {
                    v = tfround(v + bq[n]);
                    int h = n >> 6, d = n & 63;
                    g_Q[(((size_t)(b * NH + h)) * NTOK + tok) * HD + d] = v;
                } else if (n < 2 * QKDIM) {
                    int n2 = n - QKDIM;
                    v = tfround(v + bk[n2]);
                    int h = n2 >> 6, d = n2 & 63;
                    g_K[(((size_t)(b * NH + h)) * NTOK + tok) * HD + d] = v;
                } else {
                    int n2 = n - 2 * QKDIM;
                    v = tfround(v + bv[n2]);
                    int h = n2 >> 7, vd = n2 & 127;
                    g_V[(((size_t)(b * NH + h)) * NTOK + tok) * VD + vd] = v;
                }
            }
        }
    }
}

// ================================================================ Attention
// R15 structure (2m x 2n warps, K double-buffered, raw-fp32 P + tftrunc rsum,
// ex2 softmax) + NEW: slot-ordered P and sigma-permuted V rows so each warp's
// OWN key half of P@V A-fragments comes straight from its exp'd registers.
//   slot j in a row's 8-group holds key sigma(j) = ((j&3)<<1)|((j>>2)&1)
//   (i.e. C-frag col 2t -> slot t, col 2t+1 -> slot t+4: A-frag layout).
// V smem row j holds token sigma(j) of the tile -> contraction consistent.
// Partner half still flows through smem (slot-addressed, natural af form).
#define QP 68     // 68 mod 32 = 4 -> Q/K/P frag reads bank 4g+tg = lane (CF)
#define VP 136    // 136 mod 32 = 8 -> V frag reads bank 8tg+g = perm(lane) (CF)
#define P_FLOATS (64 * QP)
#define K_STAGE  (64 * QP)
#define V_FLOATS (64 * VP)
#define ATT_SMEM_BYTES ((P_FLOATS + 2 * K_STAGE + V_FLOATS) * 4)   // 87040

__global__ __launch_bounds__(128, 2)
void attn_kernel(float* __restrict__ out)
{
    extern __shared__ float sm[];
    float* Ps = sm;                       // [64][QP]  (Q staging, then P slots)
    float* Ks = sm + P_FLOATS;            // [2][64][QP]
    float* Vs = Ks + 2 * K_STAGE;         // [64][VP]  rows sigma-permuted

    const int tid = threadIdx.x;
    const int qt = blockIdx.x;            // 0..31
    const int bh = blockIdx.y;            // 0..31
    const int b = bh >> 3, h = bh & 7;

    const float* Qg = g_Q + ((size_t)bh * NTOK + qt * 64) * HD;
    const float* Kg = g_K + (size_t)bh * NTOK * HD;
    const float* Vg = g_V + (size_t)bh * NTOK * VD;

    const uint32_t ps_b = smem_u32(Ps);
    const uint32_t ks_b = smem_u32(Ks);
    const uint32_t vs_b = smem_u32(Vs);

    // Stage Q into Ps                                         [group 0: Q]
    #pragma unroll
    for (int i = 0; i < 8; i++) {
        int idx = tid + 128 * i;
        int r = idx >> 4, c4 = idx & 15;
        cp16(ps_b + (uint32_t)(r * QP + c4 * 4) * 4, Qg + (size_t)r * HD + c4 * 4);
    }
    cp_commit();

    auto loadK = [&](int t) {             // into buffer t&1
        const float* Kt = Kg + (size_t)t * 64 * HD;
        uint32_t base = ks_b + (uint32_t)((t & 1) * K_STAGE) * 4;
        #pragma unroll
        for (int i = 0; i < 8; i++) {
            int idx = tid + 128 * i;
            int r = idx >> 4, c4 = idx & 15;
            cp16(base + (uint32_t)(r * QP + c4 * 4) * 4, Kt + (size_t)r * HD + c4 * 4);
        }
        cp_commit();
    };
    auto loadV = [&](int t) {
        // smem row r holds token sigma(r) of the tile (within-8 permute)
        #pragma unroll
        for (int i = 0; i < 16; i++) {
            int idx = tid + 128 * i;
            int r = idx >> 5, c4 = idx & 31;
            int tok = (r & ~7) | (((r & 3) << 1) | ((r >> 2) & 1));
            cp16(vs_b + (uint32_t)(r * VP + c4 * 4) * 4,
                 Vg + ((size_t)t * 64 + tok) * VD + c4 * 4);
        }
        cp_commit();
    };

    loadK(0);          // group 1
    loadV(0);          // group 2
    loadK(1);          // group 3

    const int wid = tid >> 5, lane = tid & 31;
    const int g = lane >> 2, tg = lane & 3;
    const int wm = wid & 1, wn = wid >> 1;
    const int r0 = wm * 32;               // warp q-row base
    const int kc = wn * 32;               // warp S key-slot base
    const int vc = wn * 64;               // warp P@V v-column base

    // Q fragments -> registers (wait Q only; K0,V0,K1 in flight)
    asm volatile("cp.async.wait_group 3;");
    __syncthreads();
    uint32_t aq[2][8][4];
    #pragma unroll
    for (int mi = 0; mi < 2; mi++) {
        int rr = r0 + mi * 16 + g;
        #pragma unroll
        for (int ks = 0; ks < 8; ks++) {
            aq[mi][ks][0] = __float_as_uint(Ps[rr * QP + ks * 8 + tg]);
            aq[mi][ks][1] = __float_as_uint(Ps[(rr + 8) * QP + ks * 8 + tg]);
            aq[mi][ks][2] = __float_as_uint(Ps[rr * QP + ks * 8 + tg + 4]);
            aq[mi][ks][3] = __float_as_uint(Ps[(rr + 8) * QP + ks * 8 + tg + 4]);
        }
    }

    float oacc[2][8][4];
    #pragma unroll
    for (int mi = 0; mi < 2; mi++)
        #pragma unroll
        for (int ni = 0; ni < 8; ni++)
            #pragma unroll
            for (int j = 0; j < 4; j++) oacc[mi][ni][j] = 0.f;
    float rs[2][2] = {{0.f, 0.f}, {0.f, 0.f}};

    const int TT = NTOK / 64;   // 32
    for (int t = 0; t < TT; t++) {
        const float* Kt = Ks + (t & 1) * K_STAGE;

        // top: K(t) landed (V(t), K(t+1) may stay pending)
        asm volatile("cp.async.wait_group 2;");
        __syncthreads();

        // ---- S = Q @ K^T  (warp: 32 rows x 32 keys; cols = slots kc..kc+31) ----
        float s[2][4][4];
        #pragma unroll
        for (int mi = 0; mi < 2; mi++)
            #pragma unroll
            for (int ni = 0; ni < 4; ni++)
                #pragma unroll
                for (int j = 0; j < 4; j++) s[mi][ni][j] = 0.f;

        #pragma unroll
        for (int ks = 0; ks < 8; ks++) {
            #pragma unroll
            for (int ni = 0; ni < 4; ni++) {
                uint32_t bf[2];
                bf[0] = __float_as_uint(Kt[(kc + ni * 8 + g) * QP + ks * 8 + tg]);
                bf[1] = __float_as_uint(Kt[(kc + ni * 8 + g) * QP + ks * 8 + tg + 4]);
                mma_tf32(s[0][ni], aq[0][ks], bf);
                mma_tf32(s[1][ni], aq[1][ks], bf);
            }
        }

        // ---- exp in place (s becomes P); partner copy to smem SLOTS ----
        // C-frag col 2tg -> slot tg ; col 2tg+1 -> slot tg+4.
        #pragma unroll
        for (int mi = 0; mi < 2; mi++) {
            int rr = r0 + mi * 16 + g;
            #pragma unroll
            for (int ni = 0; ni < 4; ni++) {
                float e0 = ex2(s[mi][ni][0] * SC_LOG2E);
                float e1 = ex2(s[mi][ni][1] * SC_LOG2E);
                float e2 = ex2(s[mi][ni][2] * SC_LOG2E);
                float e3 = ex2(s[mi][ni][3] * SC_LOG2E);
                s[mi][ni][0] = e0; s[mi][ni][1] = e1;
                s[mi][ni][2] = e2; s[mi][ni][3] = e3;
                Ps[rr * QP + kc + ni * 8 + tg]           = e0;   // slot tg
                Ps[rr * QP + kc + ni * 8 + tg + 4]       = e1;   // slot tg+4
                Ps[(rr + 8) * QP + kc + ni * 8 + tg]     = e2;
                Ps[(rr + 8) * QP + kc + ni * 8 + tg + 4] = e3;
                rs[mi][0] += tftrunc(e0) + tftrunc(e1);
                rs[mi][1] += tftrunc(e2) + tftrunc(e3);
            }
        }

        // mid: V(t) landed; P exchange complete
        if (t + 2 < TT) { asm volatile("cp.async.wait_group 1;"); }
        else            { asm volatile("cp.async.wait_group 0;"); }
        __syncthreads();

        // ---- O += P @ V (warp: 32 rows x 64 v-cols; own half from regs) ----
        #pragma unroll
        for (int ks = 0; ks < 8; ks++) {
            uint32_t af[2][4];
            if ((ks >> 2) == wn) {
                int q = ks & 3;                       // own S ni-tile
                #pragma unroll
                for (int mi = 0; mi < 2; mi++) {
                    af[mi][0] = __float_as_uint(s[mi][q][0]);  // row rr,   k=tg
                    af[mi][1] = __float_as_uint(s[mi][q][2]);  // row rr+8, k=tg
                    af[mi][2] = __float_as_uint(s[mi][q][1]);  // row rr,   k=tg+4
                    af[mi][3] = __float_as_uint(s[mi][q][3]);  // row rr+8, k=tg+4
                }
            } else {
                #pragma unroll
                for (int mi = 0; mi < 2; mi++) {
                    int rr = r0 + mi * 16 + g;
                    af[mi][0] = __float_as_uint(Ps[rr * QP + ks * 8 + tg]);
                    af[mi][1] = __float_as_uint(Ps[(rr + 8) * QP + ks * 8 + tg]);
                    af[mi][2] = __float_as_uint(Ps[rr * QP + ks * 8 + tg + 4]);
                    af[mi][3] = __float_as_uint(Ps[(rr + 8) * QP + ks * 8 + tg + 4]);
                }
            }
            #pragma unroll
            for (int ni = 0; ni < 8; ni++) {
                uint32_t bf[2];
                bf[0] = __float_as_uint(Vs[(ks * 8 + tg) * VP + vc + ni * 8 + g]);
                bf[1] = __float_as_uint(Vs[(ks * 8 + tg + 4) * VP + vc + ni * 8 + g]);
                mma_tf32(oacc[0][ni], af[0], bf);
                mma_tf32(oacc[1][ni], af[1], bf);
            }
        }

        __syncthreads();                 // end: V + P readers done
        if (t + 1 < TT) loadV(t + 1);
        if (t + 2 < TT) loadK(t + 2);    // into buf t&1 (S(t) fenced at mid)
    }

    // ---- epilogue: row-sum reduction (intra-warp, then cross-warp via smem) ----
    #pragma unroll
    for (int mi = 0; mi < 2; mi++)
        #pragma unroll
        for (int hf = 0; hf < 2; hf++) {
            float v = rs[mi][hf];
            v += __shfl_xor_sync(0xffffffffu, v, 1);
            v += __shfl_xor_sync(0xffffffffu, v, 2);
            rs[mi][hf] = v;
        }
    float* RS = Ps;                      // Ps free after last end-sync
    if (tg == 0) {
        #pragma unroll
        for (int mi = 0; mi < 2; mi++)
            #pragma unroll
            for (int hf = 0; hf < 2; hf++)
                RS[wn * 64 + r0 + mi * 16 + hf * 8 + g] = rs[mi][hf];
    }
    __syncthreads();

    #pragma unroll
    for (int mi = 0; mi < 2; mi++) {
        int rr = r0 + mi * 16 + g;
        float inv0 = 1.f / (RS[rr] + RS[64 + rr]);
        float inv1 = 1.f / (RS[rr + 8] + RS[64 + rr + 8]);
        int tokA = qt * 64 + rr;
        float* op = out + ((size_t)b * NTOK + tokA) * OUTCH + (size_t)h * VD + vc;
        #pragma unroll
        for (int ni = 0; ni < 8; ni++) {
            int c = ni * 8 + tg * 2;
            op[c]                  = oacc[mi][ni][0] * inv0;
            op[c + 1]              = oacc[mi][ni][1] * inv0;
            op[8 * OUTCH + c]      = oacc[mi][ni][2] * inv1;
            op[8 * OUTCH + c + 1]  = oacc[mi][ni][3] * inv1;
        }
    }
}

// ================================================================ launch
extern "C" void kernel_launch(void* const* d_in, const int* in_sizes, int n_in,
                              void* d_out, int out_size)
{
    const float* x  = (const float*)d_in[0];
    const float* Wq = (const float*)d_in[1];
    const float* bq = (const float*)d_in[2];
    const float* Wk = (const float*)d_in[3];
    const float* bk = (const float*)d_in[4];
    const float* Wv = (const float*)d_in[5];
    const float* bv = (const float*)d_in[6];
    float* out = (float*)d_out;

    cudaFuncSetAttribute(qkv_gemm, cudaFuncAttributeMaxDynamicSharedMemorySize,
                         GEMM_SMEM_BYTES);
    cudaFuncSetAttribute(attn_kernel, cudaFuncAttributeMaxDynamicSharedMemorySize,
                         ATT_SMEM_BYTES);

    preround_x<<<2048, 256>>>((const float4*)x);                         // idx 0
    preround_w<<<1024, 256>>>((const float4*)Wq, (const float4*)Wk,
                              (const float4*)Wv);                        // idx 1
    dim3 g1(OUTCH * 2 / 128, (NB * NTOK) / 128);
    qkv_gemm<<<g1, 256, GEMM_SMEM_BYTES>>>(bq, bk, bv);                  // idx 2
    dim3 g2(NTOK / 64, NB * NH);
    attn_kernel<<<g2, 128, ATT_SMEM_BYTES>>>(out);                       // idx 3 -> profiled
}